// round 6
// baseline (speedup 1.0000x reference)
#include <cuda_runtime.h>
#include <math.h>

#define BB 32
#define LL 1024
#define BLT (BB*LL)
#define DIN 63
#define DM 256
#define NCLS 14
#define NLAYER 4
#define DI 512
#define DS 128
#define NHH 8
#define HPP 64
#define DCV 4
#define CCH 768
#define PRJ 1288
#define EPSF 1e-5f

// ---------------- scratch (device globals; no cudaMalloc allowed) ----------
__device__ float g_h[BLT*DM];                 // residual (k-permuted cols, fp32)
__device__ float g_hr[BLT*DM];                // residual, permuted + tf32-rounded
__device__ float g_zx[(size_t)BLT*PRJ];       // inproj output (logical cols)
__device__ float g_xbc[(size_t)BLT*CCH];      // conv+silu output
__device__ float g_dt[BLT*NHH];
__device__ float g_dA[BLT*NHH];
__device__ float g_y[(size_t)BLT*DI];         // scan out -> rms (permuted+tf32)
__device__ float g_m[BLT*DM];                 // outproj output (logical cols)
__device__ float g_poolp[8][BB*DM];           // partial pools (permuted cols)
__device__ float g_win[(size_t)NLAYER*PRJ*DM];   // permuted+rounded inproj W
__device__ float g_wout[(size_t)NLAYER*DM*DI];   // permuted+rounded outproj W

// ---------------- column permutation: kp within 32-groups -------------------
__device__ __forceinline__ int permc(int j) {
    return (j & ~31) | (((j & 3) << 3) | ((j & 31) >> 2));
}
__device__ __forceinline__ int permcinv(int j) {
    return (j & ~31) | (((j & 7) << 2) | ((j & 31) >> 3));
}

__device__ __forceinline__ float to_tf32(float x) {
    asm("cvt.rna.tf32.f32 %0, %0;" : "+f"(x));
    return x;
}

// ---------------- packed f32x2 helpers --------------------------------------
__device__ __forceinline__ unsigned long long pk2(float lo, float hi) {
    unsigned long long r;
    asm("mov.b64 %0, {%1, %2};" : "=l"(r) : "f"(lo), "f"(hi));
    return r;
}
__device__ __forceinline__ void upk2(float& lo, float& hi, unsigned long long v) {
    asm("mov.b64 {%0, %1}, %2;" : "=f"(lo), "=f"(hi) : "l"(v));
}
__device__ __forceinline__ unsigned long long mul2(unsigned long long a, unsigned long long b) {
    unsigned long long r;
    asm("mul.rn.f32x2 %0, %1, %2;" : "=l"(r) : "l"(a), "l"(b));
    return r;
}
__device__ __forceinline__ unsigned long long fma2(unsigned long long a, unsigned long long b,
                                                   unsigned long long c) {
    unsigned long long r;
    asm("fma.rn.f32x2 %0, %1, %2, %3;" : "=l"(r) : "l"(a), "l"(b), "l"(c));
    return r;
}

// ---------------- cp.async helper -------------------------------------------
__device__ __forceinline__ void cp16(void* dst, const void* src, bool v) {
    unsigned d = (unsigned)__cvta_generic_to_shared(dst);
    int sz = v ? 16 : 0;
    asm volatile("cp.async.ca.shared.global [%0], [%1], 16, %2;"
                 :: "r"(d), "l"(src), "r"(sz) : "memory");
}

// ---------------- weight permute + tf32 round pre-pass ----------------------
__global__ __launch_bounds__(256) void k_permw(const float* __restrict__ W,
                                               float* __restrict__ Wp,
                                               int total, int Kmask) {
    int i = blockIdx.x * 256 + threadIdx.x;
    if (i >= total) return;
    int k = i & Kmask;
    Wp[(i - k) + permc(k)] = to_tf32(W[i]);
}

// ---------------- block layernorm helper (blockDim == 256) -----------------
// writes full-precision to outp and tf32-rounded to outp2, both at permc(j)
__device__ __forceinline__ void ln_write256(float acc, float* outp, float* outp2,
                                            const float* __restrict__ w,
                                            const float* __restrict__ b, int j) {
    __shared__ float s1[8], s2[8];
    float v = acc, v2 = acc * acc;
    int lane = j & 31, wp = j >> 5;
#pragma unroll
    for (int o = 16; o > 0; o >>= 1) {
        v  += __shfl_down_sync(0xffffffffu, v,  o);
        v2 += __shfl_down_sync(0xffffffffu, v2, o);
    }
    if (lane == 0) { s1[wp] = v; s2[wp] = v2; }
    __syncthreads();
    if (j == 0) {
        float a = 0.f, c = 0.f;
#pragma unroll
        for (int i = 0; i < 8; i++) { a += s1[i]; c += s2[i]; }
        s1[0] = a * (1.f / DM);
        s2[0] = c * (1.f / DM);
    }
    __syncthreads();
    float mu = s1[0], var = s2[0] - mu * mu;
    float r = (acc - mu) * rsqrtf(var + EPSF) * w[j] + b[j];
    int pj = permc(j);
    outp[pj]  = r;
    outp2[pj] = to_tf32(r);
}

// ---------------- input projection + layernorm ------------------------------
__global__ __launch_bounds__(256) void k_in_ln(const float* __restrict__ x,
                                               const float* __restrict__ w,
                                               const float* __restrict__ bias,
                                               const float* __restrict__ gw,
                                               const float* __restrict__ gb) {
    int row = blockIdx.x, j = threadIdx.x;
    __shared__ float sx[DIN];
    if (j < DIN) sx[j] = x[(size_t)row * DIN + j];
    __syncthreads();
    const float* wr = w + j * DIN;
    float acc = bias[j];
#pragma unroll
    for (int k = 0; k < DIN; k++) acc += sx[k] * wr[k];
    ln_write256(acc, g_h + (size_t)row * DM, g_hr + (size_t)row * DM, gw, gb, j);
}

// ================= tf32 tensor-core GEMM: C[M,N] = A[M,K] @ B[N,K]^T =======
// Both operands pre-permuted + pre-rounded in global. Smem slabs = verbatim
// cp.async copies. 3-stage pipeline, wait_group 1 (loads run 2 slabs ahead).
// Block 128x128x32, 256 threads = 8 warps (2M x 4N).
__device__ __forceinline__ void mma8(float* c,
                                     unsigned a0, unsigned a1, unsigned a2, unsigned a3,
                                     unsigned b0, unsigned b1) {
    asm volatile(
        "mma.sync.aligned.m16n8k8.row.col.f32.tf32.tf32.f32 "
        "{%0,%1,%2,%3}, {%4,%5,%6,%7}, {%8,%9}, {%0,%1,%2,%3};"
        : "+f"(c[0]), "+f"(c[1]), "+f"(c[2]), "+f"(c[3])
        : "r"(a0), "r"(a1), "r"(a2), "r"(a3), "r"(b0), "r"(b1));
}

#define TPITCH 36
#define NST 3
#define GEMM_SMEM (NST * 2 * 128 * TPITCH * 4)   // 110592 bytes

__global__ __launch_bounds__(256, 2) void gemm_tf32(const float* __restrict__ A,
                                                    const float* __restrict__ B,
                                                    float* __restrict__ C,
                                                    int M, int N, int K) {
    extern __shared__ float smem_dyn[];
    float (*As)[128][TPITCH] = (float (*)[128][TPITCH])smem_dyn;
    float (*Bs)[128][TPITCH] = (float (*)[128][TPITCH])(smem_dyn + NST * 128 * TPITCH);

    int tid = threadIdx.x;
    int bm = blockIdx.y * 128, bn = blockIdx.x * 128;
    int lane = tid & 31, warp = tid >> 5;
    int quad = lane >> 2, tq = lane & 3;
    int wm = (warp & 1) * 64, wn = (warp >> 1) * 32;
    int rr = tid >> 3, cc = tid & 7;

    float acc[4][4][4];
#pragma unroll
    for (int i = 0; i < 4; i++)
#pragma unroll
        for (int j = 0; j < 4; j++)
#pragma unroll
            for (int f = 0; f < 4; f++) acc[i][j][f] = 0.f;

    int nIter = K >> 5;

    // prologue: issue slabs 0 and 1
#pragma unroll
    for (int s = 0; s < 2; s++) {
        int k0 = s << 5;
#pragma unroll
        for (int i = 0; i < 4; i++) {
            int r = rr + i * 32;
            cp16(&As[s][r][cc * 4], A + (size_t)(bm + r) * K + k0 + cc * 4, true);
            cp16(&Bs[s][r][cc * 4], B + (size_t)(bn + r) * K + k0 + cc * 4,
                 bn + r < N);
        }
        asm volatile("cp.async.commit_group;" ::: "memory");
    }

    int cur = 0, nxt = 2;   // nxt = (it+2) % NST
    for (int it = 0; it < nIter; it++) {
        asm volatile("cp.async.wait_group 1;" ::: "memory");
        __syncthreads();

        // issue slab it+2 into buffer nxt (freed by the barrier above)
        if (it + 2 < nIter) {
            int k0 = (it + 2) << 5;
#pragma unroll
            for (int i = 0; i < 4; i++) {
                int r = rr + i * 32;
                cp16(&As[nxt][r][cc * 4], A + (size_t)(bm + r) * K + k0 + cc * 4,
                     true);
                cp16(&Bs[nxt][r][cc * 4], B + (size_t)(bn + r) * K + k0 + cc * 4,
                     bn + r < N);
            }
            asm volatile("cp.async.commit_group;" ::: "memory");
        }

        // ---- mma on buffer cur ----
        __align__(16) unsigned bq[4][8];
#pragma unroll
        for (int j = 0; j < 4; j++) {
            const float* bp = &Bs[cur][wn + j * 8 + quad][tq * 8];
            *(float4*)&bq[j][0] = *(const float4*)bp;
            *(float4*)&bq[j][4] = *(const float4*)(bp + 4);
        }
#pragma unroll
        for (int i = 0; i < 4; i++) {
            __align__(16) unsigned alo[8], ahi[8];
            const float* ap0 = &As[cur][wm + i * 16 + quad][tq * 8];
            const float* ap1 = &As[cur][wm + i * 16 + 8 + quad][tq * 8];
            *(float4*)&alo[0] = *(const float4*)ap0;
            *(float4*)&alo[4] = *(const float4*)(ap0 + 4);
            *(float4*)&ahi[0] = *(const float4*)ap1;
            *(float4*)&ahi[4] = *(const float4*)(ap1 + 4);
#pragma unroll
            for (int j = 0; j < 4; j++)
#pragma unroll
                for (int s = 0; s < 4; s++)
                    mma8(acc[i][j], alo[2 * s], ahi[2 * s], alo[2 * s + 1],
                         ahi[2 * s + 1], bq[j][2 * s], bq[j][2 * s + 1]);
        }

        cur = (cur == NST - 1) ? 0 : cur + 1;
        nxt = (nxt == NST - 1) ? 0 : nxt + 1;
    }

    // store C (logical columns)
#pragma unroll
    for (int i = 0; i < 4; i++) {
        int row = bm + wm + i * 16 + quad;
#pragma unroll
        for (int j = 0; j < 4; j++) {
            int col = bn + wn + j * 8 + tq * 2;
            if (col < N) {
                float2 v0 = make_float2(acc[i][j][0], acc[i][j][1]);
                float2 v1 = make_float2(acc[i][j][2], acc[i][j][3]);
                *(float2*)(C + (size_t)row * N + col) = v0;
                *(float2*)(C + (size_t)(row + 8) * N + col) = v1;
            }
        }
    }
}

// ---------------- causal depthwise conv + silu ------------------------------
__global__ __launch_bounds__(256) void k_conv(const float* __restrict__ cw,
                                              const float* __restrict__ cb) {
    int idx = blockIdx.x * 256 + threadIdx.x;
    int c = idx % CCH;
    int row = idx / CCH;
    int t = row & (LL - 1);
    const float* base = g_zx + (size_t)row * PRJ + DI + c;
    float acc = cb[c];
#pragma unroll
    for (int k = 0; k < DCV; k++) {
        int tt = t + k - (DCV - 1);
        if (tt >= 0) acc += base[(long)(k - (DCV - 1)) * PRJ] * cw[k * CCH + c];
    }
    float s = acc / (1.f + expf(-acc));
    g_xbc[(size_t)row * CCH + c] = s;
}

// ---------------- dt = softplus(dt + bias), dA = exp(dt * -exp(A_log)) -----
__global__ __launch_bounds__(256) void k_dt(const float* __restrict__ dtb,
                                            const float* __restrict__ alog) {
    int idx = blockIdx.x * 256 + threadIdx.x;
    int row = idx >> 3, hh = idx & 7;
    float v = g_zx[(size_t)row * PRJ + DI + CCH + hh] + dtb[hh];
    float dt = (v > 20.f) ? v : log1pf(expf(v));
    float A = -expf(alog[hh]);
    g_dt[idx] = dt;
    g_dA[idx] = expf(dt * A);
}

// ---------------- sequential SSM scan (barrier-free, f32x2, 512 thr) --------
// one block per (b,h); 512 threads; thread tile 2(p) x 8(n); depth-1 prefetch.
__global__ __launch_bounds__(512) void k_scan(const float* __restrict__ Dp) {
    int bh = blockIdx.x, b = bh >> 3, hh = bh & 7;
    int tid = threadIdx.x;
    int pg = tid >> 4, ng = tid & 15;
    int p0 = pg * 2, n0 = ng * 8;

    unsigned long long hs[2][4];
#pragma unroll
    for (int i = 0; i < 2; i++)
#pragma unroll
        for (int j = 0; j < 4; j++) hs[i][j] = 0ull;

    const float* Bp  = g_xbc + (size_t)b * LL * CCH + DI + n0;
    const float* Cp  = Bp + DS;
    const float* Xp  = g_xbc + (size_t)b * LL * CCH + hh * HPP + p0;
    const float* dApt = g_dA + (size_t)b * LL * NHH + hh;
    const float* dtpt = g_dt + (size_t)b * LL * NHH + hh;
    const float* Zp  = g_zx + (size_t)b * LL * PRJ + hh * HPP + p0;
    float* Yp = g_y + (size_t)b * LL * DI + hh * HPP + p0;
    float Dh = Dp[hh];
    bool ldz = (ng == 0);

    // prefetch t = 0
    float4 pb0 = *(const float4*)Bp,  pb1 = *(const float4*)(Bp + 4);
    float4 pc0 = *(const float4*)Cp,  pc1 = *(const float4*)(Cp + 4);
    float2 px  = *(const float2*)Xp;
    float pdA = *dApt, pdt = *dtpt;
    float2 pz = make_float2(0.f, 0.f);
    if (ldz) pz = *(const float2*)Zp;

    for (int t = 0; t < LL; t++) {
        float4 vb0 = pb0, vb1 = pb1, vc0 = pc0, vc1 = pc1;
        float2 vx = px, vz = pz;
        float vdA = pdA, vdt = pdt;
        if (t + 1 < LL) {
            const float* nb = Bp + (size_t)(t + 1) * CCH;
            pb0 = *(const float4*)nb;
            pb1 = *(const float4*)(nb + 4);
            const float* nc = Cp + (size_t)(t + 1) * CCH;
            pc0 = *(const float4*)nc;
            pc1 = *(const float4*)(nc + 4);
            px = *(const float2*)(Xp + (size_t)(t + 1) * CCH);
            pdA = dApt[(size_t)(t + 1) * NHH];
            pdt = dtpt[(size_t)(t + 1) * NHH];
            if (ldz) pz = *(const float2*)(Zp + (size_t)(t + 1) * PRJ);
        }

        unsigned long long dA2 = pk2(vdA, vdA);
        float xa[2] = {vx.x, vx.y};
        unsigned long long bp[4], cp[4], dtx2[2], accp[2];
        bp[0] = pk2(vb0.x, vb0.y); bp[1] = pk2(vb0.z, vb0.w);
        bp[2] = pk2(vb1.x, vb1.y); bp[3] = pk2(vb1.z, vb1.w);
        cp[0] = pk2(vc0.x, vc0.y); cp[1] = pk2(vc0.z, vc0.w);
        cp[2] = pk2(vc1.x, vc1.y); cp[3] = pk2(vc1.z, vc1.w);
#pragma unroll
        for (int i = 0; i < 2; i++) {
            float d = vdt * xa[i];
            dtx2[i] = pk2(d, d);
            accp[i] = 0ull;
        }
#pragma unroll
        for (int i = 0; i < 2; i++)
#pragma unroll
            for (int j = 0; j < 4; j++) {
                hs[i][j] = fma2(dtx2[i], bp[j], mul2(hs[i][j], dA2));
                accp[i] = fma2(hs[i][j], cp[j], accp[i]);
            }
        float acc[2];
#pragma unroll
        for (int i = 0; i < 2; i++) {
            float lo, hi;
            upk2(lo, hi, accp[i]);
            acc[i] = lo + hi;
        }
#pragma unroll
        for (int o = 8; o > 0; o >>= 1)
#pragma unroll
            for (int i = 0; i < 2; i++)
                acc[i] += __shfl_down_sync(0xffffffffu, acc[i], o, 16);
        if (ldz) {
            float2 yo;
#pragma unroll
            for (int i = 0; i < 2; i++) {
                float z = (i == 0) ? vz.x : vz.y;
                float sz = z / (1.f + expf(-z));
                ((float*)&yo)[i] = (acc[i] + Dh * xa[i]) * sz;
            }
            *(float2*)(Yp + (size_t)t * DI) = yo;
        }
    }
}

// ---------------- RMS norm over 512 (in place; writes permuted + tf32) -----
__global__ __launch_bounds__(256) void k_rms(const float* __restrict__ nw) {
    int row = blockIdx.x, j = threadIdx.x;
    float a0 = g_y[(size_t)row * DI + j];
    float a1 = g_y[(size_t)row * DI + 256 + j];
    float v = a0 * a0 + a1 * a1;
    __shared__ float s1[8];
    int lane = j & 31, w = j >> 5;
#pragma unroll
    for (int o = 16; o > 0; o >>= 1) v += __shfl_down_sync(0xffffffffu, v, o);
    if (lane == 0) s1[w] = v;
    __syncthreads();
    if (j == 0) {
        float a = 0.f;
#pragma unroll
        for (int i = 0; i < 8; i++) a += s1[i];
        s1[0] = a * (1.f / DI);
    }
    __syncthreads();
    float sc = rsqrtf(s1[0] + EPSF);
    int pj = permc(j);
    g_y[(size_t)row * DI + pj]       = to_tf32(a0 * sc * nw[j]);
    g_y[(size_t)row * DI + 256 + pj] = to_tf32(a1 * sc * nw[j + 256]);
}

// ---------------- residual add + layernorm (g_h permuted in/out) ------------
__global__ __launch_bounds__(256) void k_addln(const float* __restrict__ lw,
                                               const float* __restrict__ lb) {
    int row = blockIdx.x, j = threadIdx.x;
    float acc = g_m[(size_t)row * DM + j] + g_h[(size_t)row * DM + permc(j)];
    ln_write256(acc, g_h + (size_t)row * DM, g_hr + (size_t)row * DM, lw, lb, j);
}

// ---------------- masked mean pool (permuted cols, 8 t-slices) --------------
__global__ __launch_bounds__(256) void k_pool(const int* __restrict__ lengths) {
    int b = blockIdx.x, s = blockIdx.y, d = threadIdx.x;
    int len = lengths[b];
    int t0 = s * 128;
    int t1 = min(t0 + 128, len);
    float acc = 0.f;
    const float* base = g_h + ((size_t)b * LL + t0) * DM + d;
#pragma unroll 4
    for (int t = t0; t < t1; t++, base += DM) acc += *base;
    g_poolp[s][b * DM + d] = acc;
}

// ---------------- classification head ---------------------------------------
__global__ __launch_bounds__(NCLS*32) void k_head(const float* __restrict__ hw,
                                                  const float* __restrict__ hb,
                                                  const int* __restrict__ lengths,
                                                  float* __restrict__ out) {
    int b = blockIdx.x;
    int tid = threadIdx.x, c = tid >> 5, lane = tid & 31;
    __shared__ float sp[DM];
    if (tid < DM) {
        float a = 0.f;
#pragma unroll
        for (int s = 0; s < 8; s++) a += g_poolp[s][b * DM + tid];
        sp[permcinv(tid)] = a / (float)lengths[b];
    }
    __syncthreads();
    float acc = 0.f;
    for (int k = lane; k < DM; k += 32) acc += sp[k] * hw[c * DM + k];
#pragma unroll
    for (int o = 16; o > 0; o >>= 1) acc += __shfl_down_sync(0xffffffffu, acc, o);
    if (lane == 0) out[b * NCLS + c] = acc + hb[c];
}

// ---------------- launcher ---------------------------------------------------
extern "C" void kernel_launch(void* const* d_in, const int* in_sizes, int n_in,
                              void* d_out, int out_size) {
    (void)in_sizes; (void)n_in; (void)out_size;
    const float* x        = (const float*)d_in[0];
    const float* in_w     = (const float*)d_in[1];
    const float* in_b     = (const float*)d_in[2];
    const float* lnin_w   = (const float*)d_in[3];
    const float* lnin_b   = (const float*)d_in[4];
    const float* inproj_w = (const float*)d_in[5];
    const float* conv_w   = (const float*)d_in[6];
    const float* conv_b   = (const float*)d_in[7];
    const float* dt_bias  = (const float*)d_in[8];
    const float* A_log    = (const float*)d_in[9];
    const float* Dp       = (const float*)d_in[10];
    const float* norm_w   = (const float*)d_in[11];
    const float* outp_w   = (const float*)d_in[12];
    const float* ln_w     = (const float*)d_in[13];
    const float* ln_b     = (const float*)d_in[14];
    const float* head_w   = (const float*)d_in[15];
    const float* head_b   = (const float*)d_in[16];
    const int*   lengths  = (const int*)d_in[17];
    float* out = (float*)d_out;

    float *phr, *pzx, *py, *pm, *pwin, *pwout;
    cudaGetSymbolAddress((void**)&phr,   g_hr);
    cudaGetSymbolAddress((void**)&pzx,   g_zx);
    cudaGetSymbolAddress((void**)&py,    g_y);
    cudaGetSymbolAddress((void**)&pm,    g_m);
    cudaGetSymbolAddress((void**)&pwin,  g_win);
    cudaGetSymbolAddress((void**)&pwout, g_wout);

    cudaFuncSetAttribute(gemm_tf32, cudaFuncAttributeMaxDynamicSharedMemorySize,
                         GEMM_SMEM);

    int totIn  = NLAYER * PRJ * DM;
    int totOut = NLAYER * DM * DI;
    k_permw<<<(totIn  + 255) / 256, 256>>>(inproj_w, pwin,  totIn,  DM - 1);
    k_permw<<<(totOut + 255) / 256, 256>>>(outp_w,   pwout, totOut, DI - 1);

    k_in_ln<<<BLT, 256>>>(x, in_w, in_b, lnin_w, lnin_b);
    for (int i = 0; i < NLAYER; i++) {
        gemm_tf32<<<dim3((PRJ + 127) / 128, BLT / 128), 256, GEMM_SMEM>>>(
            phr, pwin + (size_t)i * PRJ * DM, pzx, BLT, PRJ, DM);
        k_conv<<<(BLT * CCH) / 256, 256>>>(conv_w + i * DCV * CCH, conv_b + i * CCH);
        k_dt<<<(BLT * NHH) / 256, 256>>>(dt_bias + i * NHH, A_log + i * NHH);
        k_scan<<<BB * NHH, 512>>>(Dp + i * NHH);
        k_rms<<<BLT, 256>>>(norm_w + i * DI);
        gemm_tf32<<<dim3(DM / 128, BLT / 128), 256, GEMM_SMEM>>>(
            py, pwout + (size_t)i * DM * DI, pm, BLT, DM, DI);
        k_addln<<<BLT, 256>>>(ln_w + i * DM, ln_b + i * DM);
    }
    k_pool<<<dim3(BB, 8), 256>>>(lengths);
    k_head<<<BB, NCLS * 32>>>(head_w, head_b, lengths, out);
}

// round 7
// speedup vs baseline: 1.0580x; 1.0580x over previous
#include <cuda_runtime.h>
#include <math.h>

#define BB 32
#define LL 1024
#define BLT (BB*LL)
#define DIN 63
#define DM 256
#define NCLS 14
#define NLAYER 4
#define DI 512
#define DS 128
#define NHH 8
#define HPP 64
#define DCV 4
#define CCH 768
#define PRJ 1288
#define EPSF 1e-5f
#define NCH 8
#define CLEN 128
#define STATE 8192   // HPP*DS per (b,h)

// ---------------- scratch (device globals; no cudaMalloc allowed) ----------
__device__ float g_h[BLT*DM];                 // residual (k-permuted cols)
__device__ float g_zx[(size_t)BLT*PRJ];       // inproj output (logical cols)
__device__ float g_xbc[(size_t)BLT*CCH];      // conv+silu output
__device__ float g_dt[BLT*NHH];
__device__ float g_dA[BLT*NHH];
__device__ float g_y[(size_t)BLT*DI];         // y_local -> final y -> rms
__device__ float g_m[BLT*DM];                 // outproj output (logical cols)
__device__ float g_poolp[8][BB*DM];           // partial pools (permuted cols)
__device__ float g_win[(size_t)NLAYER*PRJ*DM];
__device__ float g_wout[(size_t)NLAYER*DM*DI];
__device__ float g_hend[(size_t)BB*NHH*NCH*STATE];    // chunk-end states (64MB)
__device__ float g_hstart[(size_t)BB*NHH*NCH*STATE];  // chunk-start states
__device__ float g_cumA[BB*NHH*LL];                   // dA prefix products

// ---------------- column permutation: kp within 32-groups -------------------
__device__ __forceinline__ int permc(int j) {
    return (j & ~31) | (((j & 3) << 3) | ((j & 31) >> 2));
}
__device__ __forceinline__ int permcinv(int j) {
    return (j & ~31) | (((j & 7) << 2) | ((j & 31) >> 3));
}

__device__ __forceinline__ float to_tf32(float x) {
    asm("cvt.rna.tf32.f32 %0, %0;" : "+f"(x));
    return x;
}

// ---------------- packed f32x2 helpers --------------------------------------
__device__ __forceinline__ unsigned long long pk2(float lo, float hi) {
    unsigned long long r;
    asm("mov.b64 %0, {%1, %2};" : "=l"(r) : "f"(lo), "f"(hi));
    return r;
}
__device__ __forceinline__ void upk2(float& lo, float& hi, unsigned long long v) {
    asm("mov.b64 {%0, %1}, %2;" : "=f"(lo), "=f"(hi) : "l"(v));
}
__device__ __forceinline__ unsigned long long mul2(unsigned long long a, unsigned long long b) {
    unsigned long long r;
    asm("mul.rn.f32x2 %0, %1, %2;" : "=l"(r) : "l"(a), "l"(b));
    return r;
}
__device__ __forceinline__ unsigned long long fma2(unsigned long long a, unsigned long long b,
                                                   unsigned long long c) {
    unsigned long long r;
    asm("fma.rn.f32x2 %0, %1, %2, %3;" : "=l"(r) : "l"(a), "l"(b), "l"(c));
    return r;
}

// ---------------- cp.async helper -------------------------------------------
__device__ __forceinline__ void cp16(void* dst, const void* src, bool v) {
    unsigned d = (unsigned)__cvta_generic_to_shared(dst);
    int sz = v ? 16 : 0;
    asm volatile("cp.async.ca.shared.global [%0], [%1], 16, %2;"
                 :: "r"(d), "l"(src), "r"(sz) : "memory");
}

// ---------------- weight permute + tf32 round pre-pass ----------------------
__global__ __launch_bounds__(256) void k_permw(const float* __restrict__ W,
                                               float* __restrict__ Wp,
                                               int total, int Kmask) {
    int i = blockIdx.x * 256 + threadIdx.x;
    if (i >= total) return;
    int k = i & Kmask;
    Wp[(i - k) + permc(k)] = to_tf32(W[i]);
}

// ---------------- block layernorm helper (blockDim == 256) -----------------
__device__ __forceinline__ void ln_write256(float acc, float* outp,
                                            const float* __restrict__ w,
                                            const float* __restrict__ b, int j) {
    __shared__ float s1[8], s2[8];
    float v = acc, v2 = acc * acc;
    int lane = j & 31, wp = j >> 5;
#pragma unroll
    for (int o = 16; o > 0; o >>= 1) {
        v  += __shfl_down_sync(0xffffffffu, v,  o);
        v2 += __shfl_down_sync(0xffffffffu, v2, o);
    }
    if (lane == 0) { s1[wp] = v; s2[wp] = v2; }
    __syncthreads();
    if (j == 0) {
        float a = 0.f, c = 0.f;
#pragma unroll
        for (int i = 0; i < 8; i++) { a += s1[i]; c += s2[i]; }
        s1[0] = a * (1.f / DM);
        s2[0] = c * (1.f / DM);
    }
    __syncthreads();
    float mu = s1[0], var = s2[0] - mu * mu;
    outp[permc(j)] = (acc - mu) * rsqrtf(var + EPSF) * w[j] + b[j];
}

// ---------------- input projection + layernorm ------------------------------
__global__ __launch_bounds__(256) void k_in_ln(const float* __restrict__ x,
                                               const float* __restrict__ w,
                                               const float* __restrict__ bias,
                                               const float* __restrict__ gw,
                                               const float* __restrict__ gb) {
    int row = blockIdx.x, j = threadIdx.x;
    __shared__ float sx[DIN];
    if (j < DIN) sx[j] = x[(size_t)row * DIN + j];
    __syncthreads();
    const float* wr = w + j * DIN;
    float acc = bias[j];
#pragma unroll
    for (int k = 0; k < DIN; k++) acc += sx[k] * wr[k];
    ln_write256(acc, g_h + (size_t)row * DM, gw, gb, j);
}

// ================= tf32 tensor-core GEMM (R4 proven version) ===============
__device__ __forceinline__ void mma8(float* c,
                                     unsigned a0, unsigned a1, unsigned a2, unsigned a3,
                                     unsigned b0, unsigned b1) {
    asm volatile(
        "mma.sync.aligned.m16n8k8.row.col.f32.tf32.tf32.f32 "
        "{%0,%1,%2,%3}, {%4,%5,%6,%7}, {%8,%9}, {%0,%1,%2,%3};"
        : "+f"(c[0]), "+f"(c[1]), "+f"(c[2]), "+f"(c[3])
        : "r"(a0), "r"(a1), "r"(a2), "r"(a3), "r"(b0), "r"(b1));
}

#define TPITCH 36
#define GEMM_SMEM (4 * 128 * TPITCH * 4)

template<bool CVTA>
__global__ __launch_bounds__(256, 2) void gemm_tf32(const float* __restrict__ A,
                                                    const float* __restrict__ B,
                                                    float* __restrict__ C,
                                                    int M, int N, int K) {
    extern __shared__ float smem_dyn[];
    float (*As)[128][TPITCH] = (float (*)[128][TPITCH])smem_dyn;
    float (*Bs)[128][TPITCH] = (float (*)[128][TPITCH])(smem_dyn + 2 * 128 * TPITCH);

    int tid = threadIdx.x;
    int bm = blockIdx.y * 128, bn = blockIdx.x * 128;
    int lane = tid & 31, warp = tid >> 5;
    int quad = lane >> 2, tq = lane & 3;
    int wm = (warp & 1) * 64, wn = (warp >> 1) * 32;
    int rr = tid >> 3, cc = tid & 7;

    float acc[4][4][4];
#pragma unroll
    for (int i = 0; i < 4; i++)
#pragma unroll
        for (int j = 0; j < 4; j++)
#pragma unroll
            for (int f = 0; f < 4; f++) acc[i][j][f] = 0.f;

#pragma unroll
    for (int i = 0; i < 4; i++) {
        int r = rr + i * 32;
        cp16(&Bs[0][r][cc * 4], B + (size_t)(bn + r) * K + cc * 4, bn + r < N);
        if (!CVTA)
            cp16(&As[0][r][cc * 4], A + (size_t)(bm + r) * K + cc * 4, true);
    }
    asm volatile("cp.async.commit_group;" ::: "memory");
    if (CVTA) {
#pragma unroll
        for (int i = 0; i < 4; i++) {
            float4 v = *(const float4*)(A + (size_t)(bm + rr + i * 32) * K + cc * 4);
            v.x = to_tf32(v.x); v.y = to_tf32(v.y);
            v.z = to_tf32(v.z); v.w = to_tf32(v.w);
            *(float4*)&As[0][rr + i * 32][cc * 4] = v;
        }
    }

    int nIter = K >> 5;
    for (int it = 0; it < nIter; it++) {
        int cur = it & 1, nb = cur ^ 1;
        bool more = (it + 1 < nIter);

        asm volatile("cp.async.wait_group 0;" ::: "memory");
        __syncthreads();

        if (more) {
            int k0 = (it + 1) << 5;
#pragma unroll
            for (int i = 0; i < 4; i++) {
                int r = rr + i * 32;
                cp16(&Bs[nb][r][cc * 4], B + (size_t)(bn + r) * K + k0 + cc * 4,
                     bn + r < N);
                if (!CVTA)
                    cp16(&As[nb][r][cc * 4], A + (size_t)(bm + r) * K + k0 + cc * 4,
                         true);
            }
            asm volatile("cp.async.commit_group;" ::: "memory");
        }

        __align__(16) unsigned bq[4][8];
#pragma unroll
        for (int j = 0; j < 4; j++) {
            const float* bp = &Bs[cur][wn + j * 8 + quad][tq * 8];
            *(float4*)&bq[j][0] = *(const float4*)bp;
            *(float4*)&bq[j][4] = *(const float4*)(bp + 4);
        }
#pragma unroll
        for (int i = 0; i < 4; i++) {
            __align__(16) unsigned alo[8], ahi[8];
            const float* ap0 = &As[cur][wm + i * 16 + quad][tq * 8];
            const float* ap1 = &As[cur][wm + i * 16 + 8 + quad][tq * 8];
            *(float4*)&alo[0] = *(const float4*)ap0;
            *(float4*)&alo[4] = *(const float4*)(ap0 + 4);
            *(float4*)&ahi[0] = *(const float4*)ap1;
            *(float4*)&ahi[4] = *(const float4*)(ap1 + 4);
#pragma unroll
            for (int j = 0; j < 4; j++)
#pragma unroll
                for (int s = 0; s < 4; s++)
                    mma8(acc[i][j], alo[2 * s], ahi[2 * s], alo[2 * s + 1],
                         ahi[2 * s + 1], bq[j][2 * s], bq[j][2 * s + 1]);
        }

        if (CVTA && more) {
            int k0 = (it + 1) << 5;
#pragma unroll
            for (int i = 0; i < 4; i++) {
                float4 v = *(const float4*)(A + (size_t)(bm + rr + i * 32) * K + k0 + cc * 4);
                v.x = to_tf32(v.x); v.y = to_tf32(v.y);
                v.z = to_tf32(v.z); v.w = to_tf32(v.w);
                *(float4*)&As[nb][rr + i * 32][cc * 4] = v;
            }
        }
    }

#pragma unroll
    for (int i = 0; i < 4; i++) {
        int row = bm + wm + i * 16 + quad;
#pragma unroll
        for (int j = 0; j < 4; j++) {
            int col = bn + wn + j * 8 + tq * 2;
            if (col < N) {
                float2 v0 = make_float2(acc[i][j][0], acc[i][j][1]);
                float2 v1 = make_float2(acc[i][j][2], acc[i][j][3]);
                *(float2*)(C + (size_t)row * N + col) = v0;
                *(float2*)(C + (size_t)(row + 8) * N + col) = v1;
            }
        }
    }
}

// ---------------- causal depthwise conv + silu ------------------------------
__global__ __launch_bounds__(256) void k_conv(const float* __restrict__ cw,
                                              const float* __restrict__ cb) {
    int idx = blockIdx.x * 256 + threadIdx.x;
    int c = idx % CCH;
    int row = idx / CCH;
    int t = row & (LL - 1);
    const float* base = g_zx + (size_t)row * PRJ + DI + c;
    float acc = cb[c];
#pragma unroll
    for (int k = 0; k < DCV; k++) {
        int tt = t + k - (DCV - 1);
        if (tt >= 0) acc += base[(long)(k - (DCV - 1)) * PRJ] * cw[k * CCH + c];
    }
    float s = acc / (1.f + expf(-acc));
    g_xbc[(size_t)row * CCH + c] = s;
}

// ---------------- dt = softplus(dt + bias), dA = exp(dt * -exp(A_log)) -----
__global__ __launch_bounds__(256) void k_dt(const float* __restrict__ dtb,
                                            const float* __restrict__ alog) {
    int idx = blockIdx.x * 256 + threadIdx.x;
    int row = idx >> 3, hh = idx & 7;
    float v = g_zx[(size_t)row * PRJ + DI + CCH + hh] + dtb[hh];
    float dt = (v > 20.f) ? v : log1pf(expf(v));
    float A = -expf(alog[hh]);
    g_dt[idx] = dt;
    g_dA[idx] = expf(dt * A);
}

// ================== chunked SSM scan =========================================
// h_t = cumA_t * h_chunkstart + h_local_t  =>  y_t = y_local_t + cumA_t*(C_t.h_start)
// Pass A: local scans over NCH chunks in parallel (grid bh x chunk).
// Pass B: propagate chunk-start states (grid bh, 8 sequential tiny steps).
// Pass C: correction + D*x + silu(z) epilogue (grid bh x chunk).

// ---- Pass A: local scan from h=0 over CLEN steps ---------------------------
__global__ __launch_bounds__(256) void k_scanA() {
    int chunk = blockIdx.x, bh = blockIdx.y;
    int b = bh >> 3, hh = bh & 7;
    int tid = threadIdx.x;
    int pg = tid >> 4, ng = tid & 15;
    int p0 = pg * 4, n0 = ng * 8;
    int t0 = chunk * CLEN;

    unsigned long long hs[4][4];
#pragma unroll
    for (int i = 0; i < 4; i++)
#pragma unroll
        for (int j = 0; j < 4; j++) hs[i][j] = 0ull;

    const float* Bp  = g_xbc + (size_t)(b * LL + t0) * CCH + DI + n0;
    const float* Cp  = Bp + DS;
    const float* Xp  = g_xbc + (size_t)(b * LL + t0) * CCH + hh * HPP + p0;
    const float* dApt = g_dA + (size_t)(b * LL + t0) * NHH + hh;
    const float* dtpt = g_dt + (size_t)(b * LL + t0) * NHH + hh;
    float* Yp = g_y + (size_t)(b * LL + t0) * DI + hh * HPP + p0;
    float* cAp = g_cumA + bh * LL + t0;
    float cum = 1.f;

    float4 pb0 = *(const float4*)Bp,  pb1 = *(const float4*)(Bp + 4);
    float4 pc0 = *(const float4*)Cp,  pc1 = *(const float4*)(Cp + 4);
    float4 px  = *(const float4*)Xp;
    float pdA = *dApt, pdt = *dtpt;

    for (int t = 0; t < CLEN; t++) {
        float4 vb0 = pb0, vb1 = pb1, vc0 = pc0, vc1 = pc1, vx = px;
        float vdA = pdA, vdt = pdt;
        if (t + 1 < CLEN) {
            const float* nb = Bp + (size_t)(t + 1) * CCH;
            pb0 = *(const float4*)nb;
            pb1 = *(const float4*)(nb + 4);
            const float* nc = Cp + (size_t)(t + 1) * CCH;
            pc0 = *(const float4*)nc;
            pc1 = *(const float4*)(nc + 4);
            px = *(const float4*)(Xp + (size_t)(t + 1) * CCH);
            pdA = dApt[(size_t)(t + 1) * NHH];
            pdt = dtpt[(size_t)(t + 1) * NHH];
        }

        cum *= vdA;
        if (tid == 0) cAp[t] = cum;

        unsigned long long dA2 = pk2(vdA, vdA);
        float xa[4] = {vx.x, vx.y, vx.z, vx.w};
        unsigned long long bp[4], cp[4], dtx2[4], accp[4];
        bp[0] = pk2(vb0.x, vb0.y); bp[1] = pk2(vb0.z, vb0.w);
        bp[2] = pk2(vb1.x, vb1.y); bp[3] = pk2(vb1.z, vb1.w);
        cp[0] = pk2(vc0.x, vc0.y); cp[1] = pk2(vc0.z, vc0.w);
        cp[2] = pk2(vc1.x, vc1.y); cp[3] = pk2(vc1.z, vc1.w);
#pragma unroll
        for (int i = 0; i < 4; i++) {
            float d = vdt * xa[i];
            dtx2[i] = pk2(d, d);
            accp[i] = 0ull;
        }
#pragma unroll
        for (int i = 0; i < 4; i++)
#pragma unroll
            for (int j = 0; j < 4; j++) {
                hs[i][j] = fma2(dtx2[i], bp[j], mul2(hs[i][j], dA2));
                accp[i] = fma2(hs[i][j], cp[j], accp[i]);
            }
        float acc[4];
#pragma unroll
        for (int i = 0; i < 4; i++) {
            float lo, hi;
            upk2(lo, hi, accp[i]);
            acc[i] = lo + hi;
        }
#pragma unroll
        for (int o = 8; o > 0; o >>= 1)
#pragma unroll
            for (int i = 0; i < 4; i++)
                acc[i] += __shfl_down_sync(0xffffffffu, acc[i], o, 16);
        if (ng == 0)
            *(float4*)(Yp + (size_t)t * DI) = make_float4(acc[0], acc[1], acc[2], acc[3]);
    }

    // store chunk-end state (32 floats, thread-contiguous)
    float* hp = g_hend + ((size_t)(bh * NCH + chunk)) * STATE + tid * 32;
#pragma unroll
    for (int i = 0; i < 4; i++)
#pragma unroll
        for (int j2 = 0; j2 < 2; j2++) {
            float l0, h0, l1, h1;
            upk2(l0, h0, hs[i][2 * j2]);
            upk2(l1, h1, hs[i][2 * j2 + 1]);
            *(float4*)(hp + i * 8 + j2 * 4) = make_float4(l0, h0, l1, h1);
        }
}

// ---- Pass B: chunk-start state propagation ---------------------------------
__global__ __launch_bounds__(256) void k_scanB() {
    int bh = blockIdx.x, tid = threadIdx.x;
    float4 hs[8];
#pragma unroll
    for (int k = 0; k < 8; k++) hs[k] = make_float4(0.f, 0.f, 0.f, 0.f);
#pragma unroll
    for (int c = 0; c < NCH; c++) {
        size_t base = ((size_t)(bh * NCH + c)) * STATE + tid * 32;
#pragma unroll
        for (int k = 0; k < 8; k++)
            *(float4*)(g_hstart + base + k * 4) = hs[k];
        float P = g_cumA[bh * LL + c * CLEN + CLEN - 1];
#pragma unroll
        for (int k = 0; k < 8; k++) {
            float4 e = *(const float4*)(g_hend + base + k * 4);
            hs[k].x = hs[k].x * P + e.x;
            hs[k].y = hs[k].y * P + e.y;
            hs[k].z = hs[k].z * P + e.z;
            hs[k].w = hs[k].w * P + e.w;
        }
    }
}

// ---- Pass C: correction + D*x + silu(z) ------------------------------------
__global__ __launch_bounds__(256) void k_scanC(const float* __restrict__ Dp) {
    int chunk = blockIdx.x, bh = blockIdx.y;
    int b = bh >> 3, hh = bh & 7;
    int tid = threadIdx.x;
    int pg = tid >> 4, ng = tid & 15;
    int p0 = pg * 4, n0 = ng * 8;
    int t0 = chunk * CLEN;

    // load chunk-start state
    unsigned long long hs[4][4];
    {
        const float* hp = g_hstart + ((size_t)(bh * NCH + chunk)) * STATE + tid * 32;
#pragma unroll
        for (int i = 0; i < 4; i++)
#pragma unroll
            for (int j2 = 0; j2 < 2; j2++) {
                float4 v = *(const float4*)(hp + i * 8 + j2 * 4);
                hs[i][2 * j2]     = pk2(v.x, v.y);
                hs[i][2 * j2 + 1] = pk2(v.z, v.w);
            }
    }

    const float* Cp = g_xbc + (size_t)(b * LL + t0) * CCH + DI + DS + n0;
    const float* Xp = g_xbc + (size_t)(b * LL + t0) * CCH + hh * HPP + p0;
    const float* Zp = g_zx + (size_t)(b * LL + t0) * PRJ + hh * HPP + p0;
    const float* cAp = g_cumA + bh * LL + t0;
    float* Yp = g_y + (size_t)(b * LL + t0) * DI + hh * HPP + p0;
    float Dh = Dp[hh];
    bool ldz = (ng == 0);

    float4 pc0 = *(const float4*)Cp, pc1 = *(const float4*)(Cp + 4);
    float4 py = make_float4(0.f,0.f,0.f,0.f), px = py, pz = py;
    float pcA = 0.f;
    if (ldz) {
        py = *(const float4*)Yp;
        px = *(const float4*)Xp;
        pz = *(const float4*)Zp;
        pcA = *cAp;
    }

    for (int t = 0; t < CLEN; t++) {
        float4 vc0 = pc0, vc1 = pc1, vy = py, vx = px, vz = pz;
        float vcA = pcA;
        if (t + 1 < CLEN) {
            const float* nc = Cp + (size_t)(t + 1) * CCH;
            pc0 = *(const float4*)nc;
            pc1 = *(const float4*)(nc + 4);
            if (ldz) {
                py = *(const float4*)(Yp + (size_t)(t + 1) * DI);
                px = *(const float4*)(Xp + (size_t)(t + 1) * CCH);
                pz = *(const float4*)(Zp + (size_t)(t + 1) * PRJ);
                pcA = cAp[t + 1];
            }
        }

        unsigned long long cp[4], accp[4];
        cp[0] = pk2(vc0.x, vc0.y); cp[1] = pk2(vc0.z, vc0.w);
        cp[2] = pk2(vc1.x, vc1.y); cp[3] = pk2(vc1.z, vc1.w);
#pragma unroll
        for (int i = 0; i < 4; i++) accp[i] = 0ull;
#pragma unroll
        for (int i = 0; i < 4; i++)
#pragma unroll
            for (int j = 0; j < 4; j++)
                accp[i] = fma2(hs[i][j], cp[j], accp[i]);
        float acc[4];
#pragma unroll
        for (int i = 0; i < 4; i++) {
            float lo, hi;
            upk2(lo, hi, accp[i]);
            acc[i] = lo + hi;
        }
#pragma unroll
        for (int o = 8; o > 0; o >>= 1)
#pragma unroll
            for (int i = 0; i < 4; i++)
                acc[i] += __shfl_down_sync(0xffffffffu, acc[i], o, 16);
        if (ldz) {
            float ya[4] = {vy.x, vy.y, vy.z, vy.w};
            float xa[4] = {vx.x, vx.y, vx.z, vx.w};
            float za[4] = {vz.x, vz.y, vz.z, vz.w};
            float4 yo;
            float* yv = &yo.x;
#pragma unroll
            for (int i = 0; i < 4; i++) {
                float sz = za[i] / (1.f + expf(-za[i]));
                yv[i] = (ya[i] + vcA * acc[i] + Dh * xa[i]) * sz;
            }
            *(float4*)(Yp + (size_t)t * DI) = yo;
        }
    }
}

// ---------------- RMS norm over 512 (in place; writes permuted + tf32) -----
__global__ __launch_bounds__(256) void k_rms(const float* __restrict__ nw) {
    int row = blockIdx.x, j = threadIdx.x;
    float a0 = g_y[(size_t)row * DI + j];
    float a1 = g_y[(size_t)row * DI + 256 + j];
    float v = a0 * a0 + a1 * a1;
    __shared__ float s1[8];
    int lane = j & 31, w = j >> 5;
#pragma unroll
    for (int o = 16; o > 0; o >>= 1) v += __shfl_down_sync(0xffffffffu, v, o);
    if (lane == 0) s1[w] = v;
    __syncthreads();
    if (j == 0) {
        float a = 0.f;
#pragma unroll
        for (int i = 0; i < 8; i++) a += s1[i];
        s1[0] = a * (1.f / DI);
    }
    __syncthreads();
    float sc = rsqrtf(s1[0] + EPSF);
    int pj = permc(j);
    g_y[(size_t)row * DI + pj]       = to_tf32(a0 * sc * nw[j]);
    g_y[(size_t)row * DI + 256 + pj] = to_tf32(a1 * sc * nw[j + 256]);
}

// ---------------- residual add + layernorm (g_h permuted in/out) ------------
__global__ __launch_bounds__(256) void k_addln(const float* __restrict__ lw,
                                               const float* __restrict__ lb) {
    int row = blockIdx.x, j = threadIdx.x;
    float acc = g_m[(size_t)row * DM + j] + g_h[(size_t)row * DM + permc(j)];
    ln_write256(acc, g_h + (size_t)row * DM, lw, lb, j);
}

// ---------------- masked mean pool (permuted cols, 8 t-slices) --------------
__global__ __launch_bounds__(256) void k_pool(const int* __restrict__ lengths) {
    int b = blockIdx.x, s = blockIdx.y, d = threadIdx.x;
    int len = lengths[b];
    int t0 = s * 128;
    int t1 = min(t0 + 128, len);
    float acc = 0.f;
    const float* base = g_h + ((size_t)b * LL + t0) * DM + d;
#pragma unroll 4
    for (int t = t0; t < t1; t++, base += DM) acc += *base;
    g_poolp[s][b * DM + d] = acc;
}

// ---------------- classification head ---------------------------------------
__global__ __launch_bounds__(NCLS*32) void k_head(const float* __restrict__ hw,
                                                  const float* __restrict__ hb,
                                                  const int* __restrict__ lengths,
                                                  float* __restrict__ out) {
    int b = blockIdx.x;
    int tid = threadIdx.x, c = tid >> 5, lane = tid & 31;
    __shared__ float sp[DM];
    if (tid < DM) {
        float a = 0.f;
#pragma unroll
        for (int s = 0; s < 8; s++) a += g_poolp[s][b * DM + tid];
        sp[permcinv(tid)] = a / (float)lengths[b];
    }
    __syncthreads();
    float acc = 0.f;
    for (int k = lane; k < DM; k += 32) acc += sp[k] * hw[c * DM + k];
#pragma unroll
    for (int o = 16; o > 0; o >>= 1) acc += __shfl_down_sync(0xffffffffu, acc, o);
    if (lane == 0) out[b * NCLS + c] = acc + hb[c];
}

// ---------------- launcher ---------------------------------------------------
extern "C" void kernel_launch(void* const* d_in, const int* in_sizes, int n_in,
                              void* d_out, int out_size) {
    (void)in_sizes; (void)n_in; (void)out_size;
    const float* x        = (const float*)d_in[0];
    const float* in_w     = (const float*)d_in[1];
    const float* in_b     = (const float*)d_in[2];
    const float* lnin_w   = (const float*)d_in[3];
    const float* lnin_b   = (const float*)d_in[4];
    const float* inproj_w = (const float*)d_in[5];
    const float* conv_w   = (const float*)d_in[6];
    const float* conv_b   = (const float*)d_in[7];
    const float* dt_bias  = (const float*)d_in[8];
    const float* A_log    = (const float*)d_in[9];
    const float* Dp       = (const float*)d_in[10];
    const float* norm_w   = (const float*)d_in[11];
    const float* outp_w   = (const float*)d_in[12];
    const float* ln_w     = (const float*)d_in[13];
    const float* ln_b     = (const float*)d_in[14];
    const float* head_w   = (const float*)d_in[15];
    const float* head_b   = (const float*)d_in[16];
    const int*   lengths  = (const int*)d_in[17];
    float* out = (float*)d_out;

    float *ph, *pzx, *py, *pm, *pwin, *pwout;
    cudaGetSymbolAddress((void**)&ph,    g_h);
    cudaGetSymbolAddress((void**)&pzx,   g_zx);
    cudaGetSymbolAddress((void**)&py,    g_y);
    cudaGetSymbolAddress((void**)&pm,    g_m);
    cudaGetSymbolAddress((void**)&pwin,  g_win);
    cudaGetSymbolAddress((void**)&pwout, g_wout);

    cudaFuncSetAttribute(gemm_tf32<true>,  cudaFuncAttributeMaxDynamicSharedMemorySize,
                         GEMM_SMEM);
    cudaFuncSetAttribute(gemm_tf32<false>, cudaFuncAttributeMaxDynamicSharedMemorySize,
                         GEMM_SMEM);

    int totIn  = NLAYER * PRJ * DM;
    int totOut = NLAYER * DM * DI;
    k_permw<<<(totIn  + 255) / 256, 256>>>(inproj_w, pwin,  totIn,  DM - 1);
    k_permw<<<(totOut + 255) / 256, 256>>>(outp_w,   pwout, totOut, DI - 1);

    k_in_ln<<<BLT, 256>>>(x, in_w, in_b, lnin_w, lnin_b);
    for (int i = 0; i < NLAYER; i++) {
        gemm_tf32<true><<<dim3((PRJ + 127) / 128, BLT / 128), 256, GEMM_SMEM>>>(
            ph, pwin + (size_t)i * PRJ * DM, pzx, BLT, PRJ, DM);
        k_conv<<<(BLT * CCH) / 256, 256>>>(conv_w + i * DCV * CCH, conv_b + i * CCH);
        k_dt<<<(BLT * NHH) / 256, 256>>>(dt_bias + i * NHH, A_log + i * NHH);
        k_scanA<<<dim3(NCH, BB * NHH), 256>>>();
        k_scanB<<<BB * NHH, 256>>>();
        k_scanC<<<dim3(NCH, BB * NHH), 256>>>(Dp + i * NHH);
        k_rms<<<BLT, 256>>>(norm_w + i * DI);
        gemm_tf32<false><<<dim3(DM / 128, BLT / 128), 256, GEMM_SMEM>>>(
            py, pwout + (size_t)i * DM * DI, pm, BLT, DM, DI);
        k_addln<<<BLT, 256>>>(ln_w + i * DM, ln_b + i * DM);
    }
    k_pool<<<dim3(BB, 8), 256>>>(lengths);
    k_head<<<BB, NCLS * 32>>>(head_w, head_b, lengths, out);
}

// round 8
// speedup vs baseline: 1.3197x; 1.2474x over previous
#include <cuda_runtime.h>
#include <math.h>

#define BB 32
#define LL 1024
#define BLT (BB*LL)
#define DIN 63
#define DM 256
#define NCLS 14
#define NLAYER 4
#define DI 512
#define DS 128
#define NHH 8
#define HPP 64
#define DCV 4
#define CCH 768
#define PRJ 1288
#define EPSF 1e-5f

// ---------------- scratch (device globals; no cudaMalloc allowed) ----------
__device__ float g_h[BLT*DM];                 // residual (k-permuted cols)
__device__ float g_zx[(size_t)BLT*PRJ];       // inproj output (logical cols)
__device__ float g_xbc[(size_t)BLT*CCH];      // conv+silu output
__device__ float g_dt[BLT*NHH];
__device__ float g_dA[BLT*NHH];
__device__ float g_y[(size_t)BLT*DI];         // scan out -> rms (permuted+tf32)
__device__ float g_m[BLT*DM];                 // outproj output (logical cols)
__device__ float g_poolp[8][BB*DM];           // partial pools (permuted cols)
__device__ float g_win[(size_t)NLAYER*PRJ*DM];
__device__ float g_wout[(size_t)NLAYER*DM*DI];

// ---------------- column permutation: kp within 32-groups -------------------
__device__ __forceinline__ int permc(int j) {
    return (j & ~31) | (((j & 3) << 3) | ((j & 31) >> 2));
}
__device__ __forceinline__ int permcinv(int j) {
    return (j & ~31) | (((j & 7) << 2) | ((j & 31) >> 3));
}

__device__ __forceinline__ float to_tf32(float x) {
    asm("cvt.rna.tf32.f32 %0, %0;" : "+f"(x));
    return x;
}

// ---------------- packed f32x2 helpers --------------------------------------
__device__ __forceinline__ unsigned long long pk2(float lo, float hi) {
    unsigned long long r;
    asm("mov.b64 %0, {%1, %2};" : "=l"(r) : "f"(lo), "f"(hi));
    return r;
}
__device__ __forceinline__ void upk2(float& lo, float& hi, unsigned long long v) {
    asm("mov.b64 {%0, %1}, %2;" : "=f"(lo), "=f"(hi) : "l"(v));
}
__device__ __forceinline__ unsigned long long mul2(unsigned long long a, unsigned long long b) {
    unsigned long long r;
    asm("mul.rn.f32x2 %0, %1, %2;" : "=l"(r) : "l"(a), "l"(b));
    return r;
}
__device__ __forceinline__ unsigned long long fma2(unsigned long long a, unsigned long long b,
                                                   unsigned long long c) {
    unsigned long long r;
    asm("fma.rn.f32x2 %0, %1, %2, %3;" : "=l"(r) : "l"(a), "l"(b), "l"(c));
    return r;
}

// ---------------- cp.async helpers ------------------------------------------
__device__ __forceinline__ void cp16(void* dst, const void* src, bool v) {
    unsigned d = (unsigned)__cvta_generic_to_shared(dst);
    int sz = v ? 16 : 0;
    asm volatile("cp.async.ca.shared.global [%0], [%1], 16, %2;"
                 :: "r"(d), "l"(src), "r"(sz) : "memory");
}
__device__ __forceinline__ void cp4(void* dst, const void* src) {
    unsigned d = (unsigned)__cvta_generic_to_shared(dst);
    asm volatile("cp.async.ca.shared.global [%0], [%1], 4;"
                 :: "r"(d), "l"(src) : "memory");
}

// ---------------- weight permute + tf32 round pre-pass ----------------------
__global__ __launch_bounds__(256) void k_permw(const float* __restrict__ W,
                                               float* __restrict__ Wp,
                                               int total, int Kmask) {
    int i = blockIdx.x * 256 + threadIdx.x;
    if (i >= total) return;
    int k = i & Kmask;
    Wp[(i - k) + permc(k)] = to_tf32(W[i]);
}

// ---------------- block layernorm helper (blockDim == 256) -----------------
__device__ __forceinline__ void ln_write256(float acc, float* outp,
                                            const float* __restrict__ w,
                                            const float* __restrict__ b, int j) {
    __shared__ float s1[8], s2[8];
    float v = acc, v2 = acc * acc;
    int lane = j & 31, wp = j >> 5;
#pragma unroll
    for (int o = 16; o > 0; o >>= 1) {
        v  += __shfl_down_sync(0xffffffffu, v,  o);
        v2 += __shfl_down_sync(0xffffffffu, v2, o);
    }
    if (lane == 0) { s1[wp] = v; s2[wp] = v2; }
    __syncthreads();
    if (j == 0) {
        float a = 0.f, c = 0.f;
#pragma unroll
        for (int i = 0; i < 8; i++) { a += s1[i]; c += s2[i]; }
        s1[0] = a * (1.f / DM);
        s2[0] = c * (1.f / DM);
    }
    __syncthreads();
    float mu = s1[0], var = s2[0] - mu * mu;
    outp[permc(j)] = (acc - mu) * rsqrtf(var + EPSF) * w[j] + b[j];
}

// ---------------- input projection + layernorm ------------------------------
__global__ __launch_bounds__(256) void k_in_ln(const float* __restrict__ x,
                                               const float* __restrict__ w,
                                               const float* __restrict__ bias,
                                               const float* __restrict__ gw,
                                               const float* __restrict__ gb) {
    int row = blockIdx.x, j = threadIdx.x;
    __shared__ float sx[DIN];
    if (j < DIN) sx[j] = x[(size_t)row * DIN + j];
    __syncthreads();
    const float* wr = w + j * DIN;
    float acc = bias[j];
#pragma unroll
    for (int k = 0; k < DIN; k++) acc += sx[k] * wr[k];
    ln_write256(acc, g_h + (size_t)row * DM, gw, gb, j);
}

// ================= tf32 tensor-core GEMM (R4 proven version) ===============
__device__ __forceinline__ void mma8(float* c,
                                     unsigned a0, unsigned a1, unsigned a2, unsigned a3,
                                     unsigned b0, unsigned b1) {
    asm volatile(
        "mma.sync.aligned.m16n8k8.row.col.f32.tf32.tf32.f32 "
        "{%0,%1,%2,%3}, {%4,%5,%6,%7}, {%8,%9}, {%0,%1,%2,%3};"
        : "+f"(c[0]), "+f"(c[1]), "+f"(c[2]), "+f"(c[3])
        : "r"(a0), "r"(a1), "r"(a2), "r"(a3), "r"(b0), "r"(b1));
}

#define TPITCH 36
#define GEMM_SMEM (4 * 128 * TPITCH * 4)

template<bool CVTA>
__global__ __launch_bounds__(256, 2) void gemm_tf32(const float* __restrict__ A,
                                                    const float* __restrict__ B,
                                                    float* __restrict__ C,
                                                    int M, int N, int K) {
    extern __shared__ float smem_dyn[];
    float (*As)[128][TPITCH] = (float (*)[128][TPITCH])smem_dyn;
    float (*Bs)[128][TPITCH] = (float (*)[128][TPITCH])(smem_dyn + 2 * 128 * TPITCH);

    int tid = threadIdx.x;
    int bm = blockIdx.y * 128, bn = blockIdx.x * 128;
    int lane = tid & 31, warp = tid >> 5;
    int quad = lane >> 2, tq = lane & 3;
    int wm = (warp & 1) * 64, wn = (warp >> 1) * 32;
    int rr = tid >> 3, cc = tid & 7;

    float acc[4][4][4];
#pragma unroll
    for (int i = 0; i < 4; i++)
#pragma unroll
        for (int j = 0; j < 4; j++)
#pragma unroll
            for (int f = 0; f < 4; f++) acc[i][j][f] = 0.f;

#pragma unroll
    for (int i = 0; i < 4; i++) {
        int r = rr + i * 32;
        cp16(&Bs[0][r][cc * 4], B + (size_t)(bn + r) * K + cc * 4, bn + r < N);
        if (!CVTA)
            cp16(&As[0][r][cc * 4], A + (size_t)(bm + r) * K + cc * 4, true);
    }
    asm volatile("cp.async.commit_group;" ::: "memory");
    if (CVTA) {
#pragma unroll
        for (int i = 0; i < 4; i++) {
            float4 v = *(const float4*)(A + (size_t)(bm + rr + i * 32) * K + cc * 4);
            v.x = to_tf32(v.x); v.y = to_tf32(v.y);
            v.z = to_tf32(v.z); v.w = to_tf32(v.w);
            *(float4*)&As[0][rr + i * 32][cc * 4] = v;
        }
    }

    int nIter = K >> 5;
    for (int it = 0; it < nIter; it++) {
        int cur = it & 1, nb = cur ^ 1;
        bool more = (it + 1 < nIter);

        asm volatile("cp.async.wait_group 0;" ::: "memory");
        __syncthreads();

        if (more) {
            int k0 = (it + 1) << 5;
#pragma unroll
            for (int i = 0; i < 4; i++) {
                int r = rr + i * 32;
                cp16(&Bs[nb][r][cc * 4], B + (size_t)(bn + r) * K + k0 + cc * 4,
                     bn + r < N);
                if (!CVTA)
                    cp16(&As[nb][r][cc * 4], A + (size_t)(bm + r) * K + k0 + cc * 4,
                         true);
            }
            asm volatile("cp.async.commit_group;" ::: "memory");
        }

        __align__(16) unsigned bq[4][8];
#pragma unroll
        for (int j = 0; j < 4; j++) {
            const float* bp = &Bs[cur][wn + j * 8 + quad][tq * 8];
            *(float4*)&bq[j][0] = *(const float4*)bp;
            *(float4*)&bq[j][4] = *(const float4*)(bp + 4);
        }
#pragma unroll
        for (int i = 0; i < 4; i++) {
            __align__(16) unsigned alo[8], ahi[8];
            const float* ap0 = &As[cur][wm + i * 16 + quad][tq * 8];
            const float* ap1 = &As[cur][wm + i * 16 + 8 + quad][tq * 8];
            *(float4*)&alo[0] = *(const float4*)ap0;
            *(float4*)&alo[4] = *(const float4*)(ap0 + 4);
            *(float4*)&ahi[0] = *(const float4*)ap1;
            *(float4*)&ahi[4] = *(const float4*)(ap1 + 4);
#pragma unroll
            for (int j = 0; j < 4; j++)
#pragma unroll
                for (int s = 0; s < 4; s++)
                    mma8(acc[i][j], alo[2 * s], ahi[2 * s], alo[2 * s + 1],
                         ahi[2 * s + 1], bq[j][2 * s], bq[j][2 * s + 1]);
        }

        if (CVTA && more) {
            int k0 = (it + 1) << 5;
#pragma unroll
            for (int i = 0; i < 4; i++) {
                float4 v = *(const float4*)(A + (size_t)(bm + rr + i * 32) * K + k0 + cc * 4);
                v.x = to_tf32(v.x); v.y = to_tf32(v.y);
                v.z = to_tf32(v.z); v.w = to_tf32(v.w);
                *(float4*)&As[nb][rr + i * 32][cc * 4] = v;
            }
        }
    }

#pragma unroll
    for (int i = 0; i < 4; i++) {
        int row = bm + wm + i * 16 + quad;
#pragma unroll
        for (int j = 0; j < 4; j++) {
            int col = bn + wn + j * 8 + tq * 2;
            if (col < N) {
                float2 v0 = make_float2(acc[i][j][0], acc[i][j][1]);
                float2 v1 = make_float2(acc[i][j][2], acc[i][j][3]);
                *(float2*)(C + (size_t)row * N + col) = v0;
                *(float2*)(C + (size_t)(row + 8) * N + col) = v1;
            }
        }
    }
}

// ---------------- causal depthwise conv + silu ------------------------------
__global__ __launch_bounds__(256) void k_conv(const float* __restrict__ cw,
                                              const float* __restrict__ cb) {
    int idx = blockIdx.x * 256 + threadIdx.x;
    int c = idx % CCH;
    int row = idx / CCH;
    int t = row & (LL - 1);
    const float* base = g_zx + (size_t)row * PRJ + DI + c;
    float acc = cb[c];
#pragma unroll
    for (int k = 0; k < DCV; k++) {
        int tt = t + k - (DCV - 1);
        if (tt >= 0) acc += base[(long)(k - (DCV - 1)) * PRJ] * cw[k * CCH + c];
    }
    float s = acc / (1.f + expf(-acc));
    g_xbc[(size_t)row * CCH + c] = s;
}

// ---------------- dt = softplus(dt + bias), dA = exp(dt * -exp(A_log)) -----
__global__ __launch_bounds__(256) void k_dt(const float* __restrict__ dtb,
                                            const float* __restrict__ alog) {
    int idx = blockIdx.x * 256 + threadIdx.x;
    int row = idx >> 3, hh = idx & 7;
    float v = g_zx[(size_t)row * PRJ + DI + CCH + hh] + dtb[hh];
    float dt = (v > 20.f) ? v : log1pf(expf(v));
    float A = -expf(alog[hh]);
    g_dt[idx] = dt;
    g_dA[idx] = expf(dt * A);
}

// ---------------- sequential SSM scan: cp.async smem ring, depth 7 ----------
// one block per (b,h); 256 threads = (pg 16) x (ng 16); tile 4(p) x 8(n).
// Operands staged per-step into an 8-stage smem ring by cp.async; exactly one
// commit_group per thread per step so wait_group 6 == "stage t complete".
#define NSTG 8
__global__ __launch_bounds__(256) void k_scan(const float* __restrict__ Dp) {
    __shared__ __align__(16) float sB[NSTG][DS];
    __shared__ __align__(16) float sC[NSTG][DS];
    __shared__ __align__(16) float sX[NSTG][HPP];
    __shared__ __align__(16) float sZ[NSTG][HPP];
    __shared__ float sSc[NSTG][2];

    int bh = blockIdx.x, b = bh >> 3, hh = bh & 7;
    int tid = threadIdx.x;
    int pg = tid >> 4, ng = tid & 15;
    int p0 = pg * 4, n0 = ng * 8;

    const float* xrow = g_xbc + (size_t)b * LL * CCH;
    const float* zrow = g_zx + (size_t)b * LL * PRJ + hh * HPP;
    const float* dAp  = g_dA + (size_t)b * LL * NHH + hh;
    const float* dtp  = g_dt + (size_t)b * LL * NHH + hh;
    float* yrow = g_y + (size_t)b * LL * DI + hh * HPP;
    float Dh = Dp[hh];

    unsigned long long hs[4][4];
#pragma unroll
    for (int i = 0; i < 4; i++)
#pragma unroll
        for (int j = 0; j < 4; j++) hs[i][j] = 0ull;

    // producer: stage t into ring slot t&7 (threads 0..97 carry data)
    auto issue = [&](int t) {
        int s = t & (NSTG - 1);
        const float* xr = xrow + (size_t)t * CCH;
        if (tid < 32)       cp16(&sB[s][tid * 4], xr + DI + tid * 4, true);
        else if (tid < 64)  cp16(&sC[s][(tid - 32) * 4], xr + DI + DS + (tid - 32) * 4, true);
        else if (tid < 80)  cp16(&sX[s][(tid - 64) * 4], xr + hh * HPP + (tid - 64) * 4, true);
        else if (tid < 96)  cp16(&sZ[s][(tid - 80) * 4], zrow + (size_t)t * PRJ + (tid - 80) * 4, true);
        else if (tid == 96) cp4(&sSc[s][0], dAp + (size_t)t * NHH);
        else if (tid == 97) cp4(&sSc[s][1], dtp + (size_t)t * NHH);
    };

    // prologue: stages 0..6 (7 groups per thread)
#pragma unroll
    for (int t = 0; t < NSTG - 1; t++) {
        issue(t);
        asm volatile("cp.async.commit_group;" ::: "memory");
    }

    for (int t = 0; t < LL; t++) {
        int s = t & (NSTG - 1);
        asm volatile("cp.async.wait_group 6;" ::: "memory");
        __syncthreads();

        // issue stage t+7 (slot (t-1)&7, fully consumed before last barrier)
        if (t + NSTG - 1 < LL) issue(t + NSTG - 1);
        asm volatile("cp.async.commit_group;" ::: "memory");

        // ---- consume stage s ----
        float dA = sSc[s][0], dtv = sSc[s][1];
        float4 vb0 = *(const float4*)&sB[s][n0];
        float4 vb1 = *(const float4*)&sB[s][n0 + 4];
        float4 vc0 = *(const float4*)&sC[s][n0];
        float4 vc1 = *(const float4*)&sC[s][n0 + 4];
        float4 vx  = *(const float4*)&sX[s][p0];

        unsigned long long dA2 = pk2(dA, dA);
        float xa[4] = {vx.x, vx.y, vx.z, vx.w};
        unsigned long long bp[4], cp[4], dtx2[4], accp[4];
        bp[0] = pk2(vb0.x, vb0.y); bp[1] = pk2(vb0.z, vb0.w);
        bp[2] = pk2(vb1.x, vb1.y); bp[3] = pk2(vb1.z, vb1.w);
        cp[0] = pk2(vc0.x, vc0.y); cp[1] = pk2(vc0.z, vc0.w);
        cp[2] = pk2(vc1.x, vc1.y); cp[3] = pk2(vc1.z, vc1.w);
#pragma unroll
        for (int i = 0; i < 4; i++) {
            float d = dtv * xa[i];
            dtx2[i] = pk2(d, d);
            accp[i] = 0ull;
        }
#pragma unroll
        for (int i = 0; i < 4; i++)
#pragma unroll
            for (int j = 0; j < 4; j++) {
                hs[i][j] = fma2(dtx2[i], bp[j], mul2(hs[i][j], dA2));
                accp[i] = fma2(hs[i][j], cp[j], accp[i]);
            }
        float acc[4];
#pragma unroll
        for (int i = 0; i < 4; i++) {
            float lo, hi;
            upk2(lo, hi, accp[i]);
            acc[i] = lo + hi;
        }
#pragma unroll
        for (int o = 8; o > 0; o >>= 1)
#pragma unroll
            for (int i = 0; i < 4; i++)
                acc[i] += __shfl_down_sync(0xffffffffu, acc[i], o, 16);
        if (ng == 0) {
            float4 yo;
            float* yv = &yo.x;
#pragma unroll
            for (int i = 0; i < 4; i++) {
                float z = sZ[s][p0 + i];
                float sz = z / (1.f + expf(-z));
                yv[i] = (acc[i] + Dh * xa[i]) * sz;
            }
            *(float4*)(yrow + (size_t)t * DI + p0) = yo;
        }
        __syncthreads();   // all reads of stage s done before it is refilled
    }
}

// ---------------- RMS norm over 512 (in place; writes permuted + tf32) -----
__global__ __launch_bounds__(256) void k_rms(const float* __restrict__ nw) {
    int row = blockIdx.x, j = threadIdx.x;
    float a0 = g_y[(size_t)row * DI + j];
    float a1 = g_y[(size_t)row * DI + 256 + j];
    float v = a0 * a0 + a1 * a1;
    __shared__ float s1[8];
    int lane = j & 31, w = j >> 5;
#pragma unroll
    for (int o = 16; o > 0; o >>= 1) v += __shfl_down_sync(0xffffffffu, v, o);
    if (lane == 0) s1[w] = v;
    __syncthreads();
    if (j == 0) {
        float a = 0.f;
#pragma unroll
        for (int i = 0; i < 8; i++) a += s1[i];
        s1[0] = a * (1.f / DI);
    }
    __syncthreads();
    float sc = rsqrtf(s1[0] + EPSF);
    int pj = permc(j);
    g_y[(size_t)row * DI + pj]       = to_tf32(a0 * sc * nw[j]);
    g_y[(size_t)row * DI + 256 + pj] = to_tf32(a1 * sc * nw[j + 256]);
}

// ---------------- residual add + layernorm (g_h permuted in/out) ------------
__global__ __launch_bounds__(256) void k_addln(const float* __restrict__ lw,
                                               const float* __restrict__ lb) {
    int row = blockIdx.x, j = threadIdx.x;
    float acc = g_m[(size_t)row * DM + j] + g_h[(size_t)row * DM + permc(j)];
    ln_write256(acc, g_h + (size_t)row * DM, lw, lb, j);
}

// ---------------- masked mean pool (permuted cols, 8 t-slices) --------------
__global__ __launch_bounds__(256) void k_pool(const int* __restrict__ lengths) {
    int b = blockIdx.x, s = blockIdx.y, d = threadIdx.x;
    int len = lengths[b];
    int t0 = s * 128;
    int t1 = min(t0 + 128, len);
    float acc = 0.f;
    const float* base = g_h + ((size_t)b * LL + t0) * DM + d;
#pragma unroll 4
    for (int t = t0; t < t1; t++, base += DM) acc += *base;
    g_poolp[s][b * DM + d] = acc;
}

// ---------------- classification head ---------------------------------------
__global__ __launch_bounds__(NCLS*32) void k_head(const float* __restrict__ hw,
                                                  const float* __restrict__ hb,
                                                  const int* __restrict__ lengths,
                                                  float* __restrict__ out) {
    int b = blockIdx.x;
    int tid = threadIdx.x, c = tid >> 5, lane = tid & 31;
    __shared__ float sp[DM];
    if (tid < DM) {
        float a = 0.f;
#pragma unroll
        for (int s = 0; s < 8; s++) a += g_poolp[s][b * DM + tid];
        sp[permcinv(tid)] = a / (float)lengths[b];
    }
    __syncthreads();
    float acc = 0.f;
    for (int k = lane; k < DM; k += 32) acc += sp[k] * hw[c * DM + k];
#pragma unroll
    for (int o = 16; o > 0; o >>= 1) acc += __shfl_down_sync(0xffffffffu, acc, o);
    if (lane == 0) out[b * NCLS + c] = acc + hb[c];
}

// ---------------- launcher ---------------------------------------------------
extern "C" void kernel_launch(void* const* d_in, const int* in_sizes, int n_in,
                              void* d_out, int out_size) {
    (void)in_sizes; (void)n_in; (void)out_size;
    const float* x        = (const float*)d_in[0];
    const float* in_w     = (const float*)d_in[1];
    const float* in_b     = (const float*)d_in[2];
    const float* lnin_w   = (const float*)d_in[3];
    const float* lnin_b   = (const float*)d_in[4];
    const float* inproj_w = (const float*)d_in[5];
    const float* conv_w   = (const float*)d_in[6];
    const float* conv_b   = (const float*)d_in[7];
    const float* dt_bias  = (const float*)d_in[8];
    const float* A_log    = (const float*)d_in[9];
    const float* Dp       = (const float*)d_in[10];
    const float* norm_w   = (const float*)d_in[11];
    const float* outp_w   = (const float*)d_in[12];
    const float* ln_w     = (const float*)d_in[13];
    const float* ln_b     = (const float*)d_in[14];
    const float* head_w   = (const float*)d_in[15];
    const float* head_b   = (const float*)d_in[16];
    const int*   lengths  = (const int*)d_in[17];
    float* out = (float*)d_out;

    float *ph, *pzx, *py, *pm, *pwin, *pwout;
    cudaGetSymbolAddress((void**)&ph,    g_h);
    cudaGetSymbolAddress((void**)&pzx,   g_zx);
    cudaGetSymbolAddress((void**)&py,    g_y);
    cudaGetSymbolAddress((void**)&pm,    g_m);
    cudaGetSymbolAddress((void**)&pwin,  g_win);
    cudaGetSymbolAddress((void**)&pwout, g_wout);

    cudaFuncSetAttribute(gemm_tf32<true>,  cudaFuncAttributeMaxDynamicSharedMemorySize,
                         GEMM_SMEM);
    cudaFuncSetAttribute(gemm_tf32<false>, cudaFuncAttributeMaxDynamicSharedMemorySize,
                         GEMM_SMEM);

    int totIn  = NLAYER * PRJ * DM;
    int totOut = NLAYER * DM * DI;
    k_permw<<<(totIn  + 255) / 256, 256>>>(inproj_w, pwin,  totIn,  DM - 1);
    k_permw<<<(totOut + 255) / 256, 256>>>(outp_w,   pwout, totOut, DI - 1);

    k_in_ln<<<BLT, 256>>>(x, in_w, in_b, lnin_w, lnin_b);
    for (int i = 0; i < NLAYER; i++) {
        gemm_tf32<true><<<dim3((PRJ + 127) / 128, BLT / 128), 256, GEMM_SMEM>>>(
            ph, pwin + (size_t)i * PRJ * DM, pzx, BLT, PRJ, DM);
        k_conv<<<(BLT * CCH) / 256, 256>>>(conv_w + i * DCV * CCH, conv_b + i * CCH);
        k_dt<<<(BLT * NHH) / 256, 256>>>(dt_bias + i * NHH, A_log + i * NHH);
        k_scan<<<BB * NHH, 256>>>(Dp + i * NHH);
        k_rms<<<BLT, 256>>>(norm_w + i * DI);
        gemm_tf32<false><<<dim3(DM / 128, BLT / 128), 256, GEMM_SMEM>>>(
            py, pwout + (size_t)i * DM * DI, pm, BLT, DM, DI);
        k_addln<<<BLT, 256>>>(ln_w + i * DM, ln_b + i * DM);
    }
    k_pool<<<dim3(BB, 8), 256>>>(lengths);
    k_head<<<BB, NCLS * 32>>>(head_w, head_b, lengths, out);
}

// round 9
// speedup vs baseline: 1.4762x; 1.1185x over previous
#include <cuda_runtime.h>
#include <math.h>

#define BB 32
#define LL 1024
#define BLT (BB*LL)
#define DIN 63
#define DM 256
#define NCLS 14
#define NLAYER 4
#define DI 512
#define DS 128
#define NHH 8
#define HPP 64
#define DCV 4
#define CCH 768
#define PRJ 1288
#define EPSF 1e-5f

// ---------------- scratch (device globals; no cudaMalloc allowed) ----------
__device__ float g_h[BLT*DM];                 // residual (k-permuted cols)
__device__ float g_zx[(size_t)BLT*PRJ];       // inproj output (logical cols)
__device__ float g_xbc[(size_t)BLT*CCH];      // conv+silu output
__device__ float2 g_sc[BLT*NHH];              // packed (dA, dt)
__device__ float g_y[(size_t)BLT*DI];         // scan out -> rms (permuted+tf32)
__device__ float g_m[BLT*DM];                 // outproj output (logical cols)
__device__ float g_poolp[8][BB*DM];           // partial pools (permuted cols)
__device__ float g_win[(size_t)NLAYER*PRJ*DM];
__device__ float g_wout[(size_t)NLAYER*DM*DI];

// ---------------- column permutation: kp within 32-groups -------------------
__device__ __forceinline__ int permc(int j) {
    return (j & ~31) | (((j & 3) << 3) | ((j & 31) >> 2));
}
__device__ __forceinline__ int permcinv(int j) {
    return (j & ~31) | (((j & 7) << 2) | ((j & 31) >> 3));
}

__device__ __forceinline__ float to_tf32(float x) {
    asm("cvt.rna.tf32.f32 %0, %0;" : "+f"(x));
    return x;
}

// ---------------- packed f32x2 helpers --------------------------------------
__device__ __forceinline__ unsigned long long pk2(float lo, float hi) {
    unsigned long long r;
    asm("mov.b64 %0, {%1, %2};" : "=l"(r) : "f"(lo), "f"(hi));
    return r;
}
__device__ __forceinline__ void upk2(float& lo, float& hi, unsigned long long v) {
    asm("mov.b64 {%0, %1}, %2;" : "=f"(lo), "=f"(hi) : "l"(v));
}
__device__ __forceinline__ unsigned long long mul2(unsigned long long a, unsigned long long b) {
    unsigned long long r;
    asm("mul.rn.f32x2 %0, %1, %2;" : "=l"(r) : "l"(a), "l"(b));
    return r;
}
__device__ __forceinline__ unsigned long long fma2(unsigned long long a, unsigned long long b,
                                                   unsigned long long c) {
    unsigned long long r;
    asm("fma.rn.f32x2 %0, %1, %2, %3;" : "=l"(r) : "l"(a), "l"(b), "l"(c));
    return r;
}

// ---------------- cp.async helper -------------------------------------------
__device__ __forceinline__ void cp16(void* dst, const void* src, bool v) {
    unsigned d = (unsigned)__cvta_generic_to_shared(dst);
    int sz = v ? 16 : 0;
    asm volatile("cp.async.ca.shared.global [%0], [%1], 16, %2;"
                 :: "r"(d), "l"(src), "r"(sz) : "memory");
}

// ---------------- weight permute + tf32 round pre-pass ----------------------
__global__ __launch_bounds__(256) void k_permw(const float* __restrict__ W,
                                               float* __restrict__ Wp,
                                               int total, int Kmask) {
    int i = blockIdx.x * 256 + threadIdx.x;
    if (i >= total) return;
    int k = i & Kmask;
    Wp[(i - k) + permc(k)] = to_tf32(W[i]);
}

// ---------------- block layernorm helper (blockDim == 256) -----------------
__device__ __forceinline__ void ln_write256(float acc, float* outp,
                                            const float* __restrict__ w,
                                            const float* __restrict__ b, int j) {
    __shared__ float s1[8], s2[8];
    float v = acc, v2 = acc * acc;
    int lane = j & 31, wp = j >> 5;
#pragma unroll
    for (int o = 16; o > 0; o >>= 1) {
        v  += __shfl_down_sync(0xffffffffu, v,  o);
        v2 += __shfl_down_sync(0xffffffffu, v2, o);
    }
    if (lane == 0) { s1[wp] = v; s2[wp] = v2; }
    __syncthreads();
    if (j == 0) {
        float a = 0.f, c = 0.f;
#pragma unroll
        for (int i = 0; i < 8; i++) { a += s1[i]; c += s2[i]; }
        s1[0] = a * (1.f / DM);
        s2[0] = c * (1.f / DM);
    }
    __syncthreads();
    float mu = s1[0], var = s2[0] - mu * mu;
    outp[permc(j)] = (acc - mu) * rsqrtf(var + EPSF) * w[j] + b[j];
}

// ---------------- input projection + layernorm ------------------------------
__global__ __launch_bounds__(256) void k_in_ln(const float* __restrict__ x,
                                               const float* __restrict__ w,
                                               const float* __restrict__ bias,
                                               const float* __restrict__ gw,
                                               const float* __restrict__ gb) {
    int row = blockIdx.x, j = threadIdx.x;
    __shared__ float sx[DIN];
    if (j < DIN) sx[j] = x[(size_t)row * DIN + j];
    __syncthreads();
    const float* wr = w + j * DIN;
    float acc = bias[j];
#pragma unroll
    for (int k = 0; k < DIN; k++) acc += sx[k] * wr[k];
    ln_write256(acc, g_h + (size_t)row * DM, gw, gb, j);
}

// ================= tf32 tensor-core GEMM (R4 proven version) ===============
__device__ __forceinline__ void mma8(float* c,
                                     unsigned a0, unsigned a1, unsigned a2, unsigned a3,
                                     unsigned b0, unsigned b1) {
    asm volatile(
        "mma.sync.aligned.m16n8k8.row.col.f32.tf32.tf32.f32 "
        "{%0,%1,%2,%3}, {%4,%5,%6,%7}, {%8,%9}, {%0,%1,%2,%3};"
        : "+f"(c[0]), "+f"(c[1]), "+f"(c[2]), "+f"(c[3])
        : "r"(a0), "r"(a1), "r"(a2), "r"(a3), "r"(b0), "r"(b1));
}

#define TPITCH 36
#define GEMM_SMEM (4 * 128 * TPITCH * 4)

template<bool CVTA>
__global__ __launch_bounds__(256, 2) void gemm_tf32(const float* __restrict__ A,
                                                    const float* __restrict__ B,
                                                    float* __restrict__ C,
                                                    int M, int N, int K) {
    extern __shared__ float smem_dyn[];
    float (*As)[128][TPITCH] = (float (*)[128][TPITCH])smem_dyn;
    float (*Bs)[128][TPITCH] = (float (*)[128][TPITCH])(smem_dyn + 2 * 128 * TPITCH);

    int tid = threadIdx.x;
    int bm = blockIdx.y * 128, bn = blockIdx.x * 128;
    int lane = tid & 31, warp = tid >> 5;
    int quad = lane >> 2, tq = lane & 3;
    int wm = (warp & 1) * 64, wn = (warp >> 1) * 32;
    int rr = tid >> 3, cc = tid & 7;

    float acc[4][4][4];
#pragma unroll
    for (int i = 0; i < 4; i++)
#pragma unroll
        for (int j = 0; j < 4; j++)
#pragma unroll
            for (int f = 0; f < 4; f++) acc[i][j][f] = 0.f;

#pragma unroll
    for (int i = 0; i < 4; i++) {
        int r = rr + i * 32;
        cp16(&Bs[0][r][cc * 4], B + (size_t)(bn + r) * K + cc * 4, bn + r < N);
        if (!CVTA)
            cp16(&As[0][r][cc * 4], A + (size_t)(bm + r) * K + cc * 4, true);
    }
    asm volatile("cp.async.commit_group;" ::: "memory");
    if (CVTA) {
#pragma unroll
        for (int i = 0; i < 4; i++) {
            float4 v = *(const float4*)(A + (size_t)(bm + rr + i * 32) * K + cc * 4);
            v.x = to_tf32(v.x); v.y = to_tf32(v.y);
            v.z = to_tf32(v.z); v.w = to_tf32(v.w);
            *(float4*)&As[0][rr + i * 32][cc * 4] = v;
        }
    }

    int nIter = K >> 5;
    for (int it = 0; it < nIter; it++) {
        int cur = it & 1, nb = cur ^ 1;
        bool more = (it + 1 < nIter);

        asm volatile("cp.async.wait_group 0;" ::: "memory");
        __syncthreads();

        if (more) {
            int k0 = (it + 1) << 5;
#pragma unroll
            for (int i = 0; i < 4; i++) {
                int r = rr + i * 32;
                cp16(&Bs[nb][r][cc * 4], B + (size_t)(bn + r) * K + k0 + cc * 4,
                     bn + r < N);
                if (!CVTA)
                    cp16(&As[nb][r][cc * 4], A + (size_t)(bm + r) * K + k0 + cc * 4,
                         true);
            }
            asm volatile("cp.async.commit_group;" ::: "memory");
        }

        __align__(16) unsigned bq[4][8];
#pragma unroll
        for (int j = 0; j < 4; j++) {
            const float* bp = &Bs[cur][wn + j * 8 + quad][tq * 8];
            *(float4*)&bq[j][0] = *(const float4*)bp;
            *(float4*)&bq[j][4] = *(const float4*)(bp + 4);
        }
#pragma unroll
        for (int i = 0; i < 4; i++) {
            __align__(16) unsigned alo[8], ahi[8];
            const float* ap0 = &As[cur][wm + i * 16 + quad][tq * 8];
            const float* ap1 = &As[cur][wm + i * 16 + 8 + quad][tq * 8];
            *(float4*)&alo[0] = *(const float4*)ap0;
            *(float4*)&alo[4] = *(const float4*)(ap0 + 4);
            *(float4*)&ahi[0] = *(const float4*)ap1;
            *(float4*)&ahi[4] = *(const float4*)(ap1 + 4);
#pragma unroll
            for (int j = 0; j < 4; j++)
#pragma unroll
                for (int s = 0; s < 4; s++)
                    mma8(acc[i][j], alo[2 * s], ahi[2 * s], alo[2 * s + 1],
                         ahi[2 * s + 1], bq[j][2 * s], bq[j][2 * s + 1]);
        }

        if (CVTA && more) {
            int k0 = (it + 1) << 5;
#pragma unroll
            for (int i = 0; i < 4; i++) {
                float4 v = *(const float4*)(A + (size_t)(bm + rr + i * 32) * K + k0 + cc * 4);
                v.x = to_tf32(v.x); v.y = to_tf32(v.y);
                v.z = to_tf32(v.z); v.w = to_tf32(v.w);
                *(float4*)&As[nb][rr + i * 32][cc * 4] = v;
            }
        }
    }

#pragma unroll
    for (int i = 0; i < 4; i++) {
        int row = bm + wm + i * 16 + quad;
#pragma unroll
        for (int j = 0; j < 4; j++) {
            int col = bn + wn + j * 8 + tq * 2;
            if (col < N) {
                float2 v0 = make_float2(acc[i][j][0], acc[i][j][1]);
                float2 v1 = make_float2(acc[i][j][2], acc[i][j][3]);
                *(float2*)(C + (size_t)row * N + col) = v0;
                *(float2*)(C + (size_t)(row + 8) * N + col) = v1;
            }
        }
    }
}

// ---------------- causal depthwise conv + silu ------------------------------
__global__ __launch_bounds__(256) void k_conv(const float* __restrict__ cw,
                                              const float* __restrict__ cb) {
    int idx = blockIdx.x * 256 + threadIdx.x;
    int c = idx % CCH;
    int row = idx / CCH;
    int t = row & (LL - 1);
    const float* base = g_zx + (size_t)row * PRJ + DI + c;
    float acc = cb[c];
#pragma unroll
    for (int k = 0; k < DCV; k++) {
        int tt = t + k - (DCV - 1);
        if (tt >= 0) acc += base[(long)(k - (DCV - 1)) * PRJ] * cw[k * CCH + c];
    }
    float s = acc / (1.f + expf(-acc));
    g_xbc[(size_t)row * CCH + c] = s;
}

// ---------------- dt/dA: packed (dA, dt) float2 -----------------------------
__global__ __launch_bounds__(256) void k_dt(const float* __restrict__ dtb,
                                            const float* __restrict__ alog) {
    int idx = blockIdx.x * 256 + threadIdx.x;
    int row = idx >> 3, hh = idx & 7;
    float v = g_zx[(size_t)row * PRJ + DI + CCH + hh] + dtb[hh];
    float dt = (v > 20.f) ? v : log1pf(expf(v));
    float A = -expf(alog[hh]);
    g_sc[idx] = make_float2(expf(dt * A), dt);
}

// ---------------- sequential SSM scan (R4 structure, pointer-incremented) ---
// one block per (b,h); 256 threads; thread tile 4(p) x 8(n); depth-1 prefetch.
// All per-step operands come off ONE running xBC-row pointer (B/C/x at fixed
// offsets), one float2 scalar pointer, and (ng==0 only) z/y pointers.
__global__ __launch_bounds__(256) void k_scan(const float* __restrict__ Dp) {
    int bh = blockIdx.x, b = bh >> 3, hh = bh & 7;
    int tid = threadIdx.x;
    int pg = tid >> 4, ng = tid & 15;
    int p0 = pg * 4, n0 = ng * 8;

    unsigned long long hs[4][4];
#pragma unroll
    for (int i = 0; i < 4; i++)
#pragma unroll
        for (int j = 0; j < 4; j++) hs[i][j] = 0ull;

    // single running pointer for the xBC row; fixed offsets select B/C/x
    const float* xr = g_xbc + (size_t)b * LL * CCH;
    const int OB = DI + n0;          // B slice offset
    const int OC = DI + DS + n0;     // C slice offset
    const int OX = hh * HPP + p0;    // x slice offset
    const float2* scp = g_sc + (size_t)b * LL * NHH + hh;
    const float* zp = g_zx + (size_t)b * LL * PRJ + hh * HPP + p0;
    float* yp = g_y + (size_t)b * LL * DI + hh * HPP + p0;
    float Dh = Dp[hh];
    bool ldz = (ng == 0);

    // prefetch t = 0
    float4 pb0 = *(const float4*)(xr + OB);
    float4 pb1 = *(const float4*)(xr + OB + 4);
    float4 pc0 = *(const float4*)(xr + OC);
    float4 pc1 = *(const float4*)(xr + OC + 4);
    float4 px  = *(const float4*)(xr + OX);
    float2 psc = *scp;
    float4 pz = make_float4(0.f, 0.f, 0.f, 0.f);
    if (ldz) pz = *(const float4*)zp;

    for (int t = 0; t < LL; t++) {
        float4 vb0 = pb0, vb1 = pb1, vc0 = pc0, vc1 = pc1, vx = px, vz = pz;
        float2 vsc = psc;
        if (t + 1 < LL) {
            xr += CCH;
            scp += NHH;
            pb0 = *(const float4*)(xr + OB);
            pb1 = *(const float4*)(xr + OB + 4);
            pc0 = *(const float4*)(xr + OC);
            pc1 = *(const float4*)(xr + OC + 4);
            px  = *(const float4*)(xr + OX);
            psc = *scp;
            if (ldz) pz = *(const float4*)(zp + PRJ);
        }

        unsigned long long dA2 = pk2(vsc.x, vsc.x);
        float xa[4] = {vx.x, vx.y, vx.z, vx.w};
        unsigned long long bp[4], cp[4], dtx2[4], accp[4];
        bp[0] = pk2(vb0.x, vb0.y); bp[1] = pk2(vb0.z, vb0.w);
        bp[2] = pk2(vb1.x, vb1.y); bp[3] = pk2(vb1.z, vb1.w);
        cp[0] = pk2(vc0.x, vc0.y); cp[1] = pk2(vc0.z, vc0.w);
        cp[2] = pk2(vc1.x, vc1.y); cp[3] = pk2(vc1.z, vc1.w);
#pragma unroll
        for (int i = 0; i < 4; i++) {
            float d = vsc.y * xa[i];
            dtx2[i] = pk2(d, d);
            accp[i] = 0ull;
        }
#pragma unroll
        for (int i = 0; i < 4; i++)
#pragma unroll
            for (int j = 0; j < 4; j++) {
                hs[i][j] = fma2(dtx2[i], bp[j], mul2(hs[i][j], dA2));
                accp[i] = fma2(hs[i][j], cp[j], accp[i]);
            }
        float acc[4];
#pragma unroll
        for (int i = 0; i < 4; i++) {
            float lo, hi;
            upk2(lo, hi, accp[i]);
            acc[i] = lo + hi;
        }
#pragma unroll
        for (int o = 8; o > 0; o >>= 1)
#pragma unroll
            for (int i = 0; i < 4; i++)
                acc[i] += __shfl_down_sync(0xffffffffu, acc[i], o, 16);
        if (ldz) {
            float za[4] = {vz.x, vz.y, vz.z, vz.w};
            float4 yo;
            float* yv = &yo.x;
#pragma unroll
            for (int i = 0; i < 4; i++) {
                float sz = za[i] / (1.f + expf(-za[i]));
                yv[i] = (acc[i] + Dh * xa[i]) * sz;
            }
            *(float4*)yp = yo;
            zp += PRJ;
            yp += DI;
        }
    }
}

// ---------------- RMS norm over 512 (in place; writes permuted + tf32) -----
__global__ __launch_bounds__(256) void k_rms(const float* __restrict__ nw) {
    int row = blockIdx.x, j = threadIdx.x;
    float a0 = g_y[(size_t)row * DI + j];
    float a1 = g_y[(size_t)row * DI + 256 + j];
    float v = a0 * a0 + a1 * a1;
    __shared__ float s1[8];
    int lane = j & 31, w = j >> 5;
#pragma unroll
    for (int o = 16; o > 0; o >>= 1) v += __shfl_down_sync(0xffffffffu, v, o);
    if (lane == 0) s1[w] = v;
    __syncthreads();
    if (j == 0) {
        float a = 0.f;
#pragma unroll
        for (int i = 0; i < 8; i++) a += s1[i];
        s1[0] = a * (1.f / DI);
    }
    __syncthreads();
    float sc = rsqrtf(s1[0] + EPSF);
    int pj = permc(j);
    g_y[(size_t)row * DI + pj]       = to_tf32(a0 * sc * nw[j]);
    g_y[(size_t)row * DI + 256 + pj] = to_tf32(a1 * sc * nw[j + 256]);
}

// ---------------- residual add + layernorm (g_h permuted in/out) ------------
__global__ __launch_bounds__(256) void k_addln(const float* __restrict__ lw,
                                               const float* __restrict__ lb) {
    int row = blockIdx.x, j = threadIdx.x;
    float acc = g_m[(size_t)row * DM + j] + g_h[(size_t)row * DM + permc(j)];
    ln_write256(acc, g_h + (size_t)row * DM, lw, lb, j);
}

// ---------------- masked mean pool (permuted cols, 8 t-slices) --------------
__global__ __launch_bounds__(256) void k_pool(const int* __restrict__ lengths) {
    int b = blockIdx.x, s = blockIdx.y, d = threadIdx.x;
    int len = lengths[b];
    int t0 = s * 128;
    int t1 = min(t0 + 128, len);
    float acc = 0.f;
    const float* base = g_h + ((size_t)b * LL + t0) * DM + d;
#pragma unroll 4
    for (int t = t0; t < t1; t++, base += DM) acc += *base;
    g_poolp[s][b * DM + d] = acc;
}

// ---------------- classification head ---------------------------------------
__global__ __launch_bounds__(NCLS*32) void k_head(const float* __restrict__ hw,
                                                  const float* __restrict__ hb,
                                                  const int* __restrict__ lengths,
                                                  float* __restrict__ out) {
    int b = blockIdx.x;
    int tid = threadIdx.x, c = tid >> 5, lane = tid & 31;
    __shared__ float sp[DM];
    if (tid < DM) {
        float a = 0.f;
#pragma unroll
        for (int s = 0; s < 8; s++) a += g_poolp[s][b * DM + tid];
        sp[permcinv(tid)] = a / (float)lengths[b];
    }
    __syncthreads();
    float acc = 0.f;
    for (int k = lane; k < DM; k += 32) acc += sp[k] * hw[c * DM + k];
#pragma unroll
    for (int o = 16; o > 0; o >>= 1) acc += __shfl_down_sync(0xffffffffu, acc, o);
    if (lane == 0) out[b * NCLS + c] = acc + hb[c];
}

// ---------------- launcher ---------------------------------------------------
extern "C" void kernel_launch(void* const* d_in, const int* in_sizes, int n_in,
                              void* d_out, int out_size) {
    (void)in_sizes; (void)n_in; (void)out_size;
    const float* x        = (const float*)d_in[0];
    const float* in_w     = (const float*)d_in[1];
    const float* in_b     = (const float*)d_in[2];
    const float* lnin_w   = (const float*)d_in[3];
    const float* lnin_b   = (const float*)d_in[4];
    const float* inproj_w = (const float*)d_in[5];
    const float* conv_w   = (const float*)d_in[6];
    const float* conv_b   = (const float*)d_in[7];
    const float* dt_bias  = (const float*)d_in[8];
    const float* A_log    = (const float*)d_in[9];
    const float* Dp       = (const float*)d_in[10];
    const float* norm_w   = (const float*)d_in[11];
    const float* outp_w   = (const float*)d_in[12];
    const float* ln_w     = (const float*)d_in[13];
    const float* ln_b     = (const float*)d_in[14];
    const float* head_w   = (const float*)d_in[15];
    const float* head_b   = (const float*)d_in[16];
    const int*   lengths  = (const int*)d_in[17];
    float* out = (float*)d_out;

    float *ph, *pzx, *py, *pm, *pwin, *pwout;
    cudaGetSymbolAddress((void**)&ph,    g_h);
    cudaGetSymbolAddress((void**)&pzx,   g_zx);
    cudaGetSymbolAddress((void**)&py,    g_y);
    cudaGetSymbolAddress((void**)&pm,    g_m);
    cudaGetSymbolAddress((void**)&pwin,  g_win);
    cudaGetSymbolAddress((void**)&pwout, g_wout);

    cudaFuncSetAttribute(gemm_tf32<true>,  cudaFuncAttributeMaxDynamicSharedMemorySize,
                         GEMM_SMEM);
    cudaFuncSetAttribute(gemm_tf32<false>, cudaFuncAttributeMaxDynamicSharedMemorySize,
                         GEMM_SMEM);

    int totIn  = NLAYER * PRJ * DM;
    int totOut = NLAYER * DM * DI;
    k_permw<<<(totIn  + 255) / 256, 256>>>(inproj_w, pwin,  totIn,  DM - 1);
    k_permw<<<(totOut + 255) / 256, 256>>>(outp_w,   pwout, totOut, DI - 1);

    k_in_ln<<<BLT, 256>>>(x, in_w, in_b, lnin_w, lnin_b);
    for (int i = 0; i < NLAYER; i++) {
        gemm_tf32<true><<<dim3((PRJ + 127) / 128, BLT / 128), 256, GEMM_SMEM>>>(
            ph, pwin + (size_t)i * PRJ * DM, pzx, BLT, PRJ, DM);
        k_conv<<<(BLT * CCH) / 256, 256>>>(conv_w + i * DCV * CCH, conv_b + i * CCH);
        k_dt<<<(BLT * NHH) / 256, 256>>>(dt_bias + i * NHH, A_log + i * NHH);
        k_scan<<<BB * NHH, 256>>>(Dp + i * NHH);
        k_rms<<<BLT, 256>>>(norm_w + i * DI);
        gemm_tf32<false><<<dim3(DM / 128, BLT / 128), 256, GEMM_SMEM>>>(
            py, pwout + (size_t)i * DM * DI, pm, BLT, DM, DI);
        k_addln<<<BLT, 256>>>(ln_w + i * DM, ln_b + i * DM);
    }
    k_pool<<<dim3(BB, 8), 256>>>(lengths);
    k_head<<<BB, NCLS * 32>>>(head_w, head_b, lengths, out);
}

// round 10
// speedup vs baseline: 1.5090x; 1.0222x over previous
#include <cuda_runtime.h>
#include <math.h>

#define BB 32
#define LL 1024
#define BLT (BB*LL)
#define DIN 63
#define DM 256
#define NCLS 14
#define NLAYER 4
#define DI 512
#define DS 128
#define NHH 8
#define HPP 64
#define DCV 4
#define CCH 768
#define PRJ 1288
#define EPSF 1e-5f

// ---------------- scratch (device globals; no cudaMalloc allowed) ----------
__device__ float g_h[BLT*DM];                 // residual (k-permuted cols)
__device__ float g_zx[(size_t)BLT*PRJ];       // inproj output (logical cols)
__device__ float g_xbc[(size_t)BLT*CCH];      // conv+silu output
__device__ float2 g_sc[BLT*NHH];              // packed (dA, dt)
__device__ float g_y[(size_t)BLT*DI];         // scan out -> rms (permuted+tf32)
__device__ float g_m[BLT*DM];                 // outproj output (logical cols)
__device__ float g_poolp[8][BB*DM];           // partial pools (permuted cols)
__device__ float g_win[(size_t)NLAYER*PRJ*DM];
__device__ float g_wout[(size_t)NLAYER*DM*DI];

// ---------------- column permutation: kp within 32-groups -------------------
__device__ __forceinline__ int permc(int j) {
    return (j & ~31) | (((j & 3) << 3) | ((j & 31) >> 2));
}
__device__ __forceinline__ int permcinv(int j) {
    return (j & ~31) | (((j & 7) << 2) | ((j & 31) >> 3));
}

__device__ __forceinline__ float to_tf32(float x) {
    asm("cvt.rna.tf32.f32 %0, %0;" : "+f"(x));
    return x;
}

// ---------------- fast silu: sigmoid via tanh.approx (1 MUFU) --------------
__device__ __forceinline__ float tanh_ap(float x) {
    float r;
    asm("tanh.approx.f32 %0, %1;" : "=f"(r) : "f"(x));
    return r;
}
__device__ __forceinline__ float silu_f(float x) {
    // x * sigmoid(x); sigmoid(x) = 0.5*tanh(x/2) + 0.5
    return x * fmaf(0.5f, tanh_ap(0.5f * x), 0.5f);
}

// ---------------- packed f32x2 helpers --------------------------------------
__device__ __forceinline__ unsigned long long pk2(float lo, float hi) {
    unsigned long long r;
    asm("mov.b64 %0, {%1, %2};" : "=l"(r) : "f"(lo), "f"(hi));
    return r;
}
__device__ __forceinline__ void upk2(float& lo, float& hi, unsigned long long v) {
    asm("mov.b64 {%0, %1}, %2;" : "=f"(lo), "=f"(hi) : "l"(v));
}
__device__ __forceinline__ unsigned long long mul2(unsigned long long a, unsigned long long b) {
    unsigned long long r;
    asm("mul.rn.f32x2 %0, %1, %2;" : "=l"(r) : "l"(a), "l"(b));
    return r;
}
__device__ __forceinline__ unsigned long long fma2(unsigned long long a, unsigned long long b,
                                                   unsigned long long c) {
    unsigned long long r;
    asm("fma.rn.f32x2 %0, %1, %2, %3;" : "=l"(r) : "l"(a), "l"(b), "l"(c));
    return r;
}

// ---------------- cp.async helper -------------------------------------------
__device__ __forceinline__ void cp16(void* dst, const void* src, bool v) {
    unsigned d = (unsigned)__cvta_generic_to_shared(dst);
    int sz = v ? 16 : 0;
    asm volatile("cp.async.ca.shared.global [%0], [%1], 16, %2;"
                 :: "r"(d), "l"(src), "r"(sz) : "memory");
}

// ---------------- weight permute + tf32 round pre-pass ----------------------
__global__ __launch_bounds__(256) void k_permw(const float* __restrict__ W,
                                               float* __restrict__ Wp,
                                               int total, int Kmask) {
    int i = blockIdx.x * 256 + threadIdx.x;
    if (i >= total) return;
    int k = i & Kmask;
    Wp[(i - k) + permc(k)] = to_tf32(W[i]);
}

// ---------------- block layernorm helper (blockDim == 256) -----------------
__device__ __forceinline__ void ln_write256(float acc, float* outp,
                                            const float* __restrict__ w,
                                            const float* __restrict__ b, int j) {
    __shared__ float s1[8], s2[8];
    float v = acc, v2 = acc * acc;
    int lane = j & 31, wp = j >> 5;
#pragma unroll
    for (int o = 16; o > 0; o >>= 1) {
        v  += __shfl_down_sync(0xffffffffu, v,  o);
        v2 += __shfl_down_sync(0xffffffffu, v2, o);
    }
    if (lane == 0) { s1[wp] = v; s2[wp] = v2; }
    __syncthreads();
    if (j == 0) {
        float a = 0.f, c = 0.f;
#pragma unroll
        for (int i = 0; i < 8; i++) { a += s1[i]; c += s2[i]; }
        s1[0] = a * (1.f / DM);
        s2[0] = c * (1.f / DM);
    }
    __syncthreads();
    float mu = s1[0], var = s2[0] - mu * mu;
    outp[permc(j)] = (acc - mu) * rsqrtf(var + EPSF) * w[j] + b[j];
}

// ---------------- input projection + layernorm ------------------------------
__global__ __launch_bounds__(256) void k_in_ln(const float* __restrict__ x,
                                               const float* __restrict__ w,
                                               const float* __restrict__ bias,
                                               const float* __restrict__ gw,
                                               const float* __restrict__ gb) {
    int row = blockIdx.x, j = threadIdx.x;
    __shared__ float sx[DIN];
    if (j < DIN) sx[j] = x[(size_t)row * DIN + j];
    __syncthreads();
    const float* wr = w + j * DIN;
    float acc = bias[j];
#pragma unroll
    for (int k = 0; k < DIN; k++) acc += sx[k] * wr[k];
    ln_write256(acc, g_h + (size_t)row * DM, gw, gb, j);
}

// ================= tf32 tensor-core GEMM (R4 proven version) ===============
__device__ __forceinline__ void mma8(float* c,
                                     unsigned a0, unsigned a1, unsigned a2, unsigned a3,
                                     unsigned b0, unsigned b1) {
    asm volatile(
        "mma.sync.aligned.m16n8k8.row.col.f32.tf32.tf32.f32 "
        "{%0,%1,%2,%3}, {%4,%5,%6,%7}, {%8,%9}, {%0,%1,%2,%3};"
        : "+f"(c[0]), "+f"(c[1]), "+f"(c[2]), "+f"(c[3])
        : "r"(a0), "r"(a1), "r"(a2), "r"(a3), "r"(b0), "r"(b1));
}

#define TPITCH 36
#define GEMM_SMEM (4 * 128 * TPITCH * 4)

template<bool CVTA>
__global__ __launch_bounds__(256, 2) void gemm_tf32(const float* __restrict__ A,
                                                    const float* __restrict__ B,
                                                    float* __restrict__ C,
                                                    int M, int N, int K) {
    extern __shared__ float smem_dyn[];
    float (*As)[128][TPITCH] = (float (*)[128][TPITCH])smem_dyn;
    float (*Bs)[128][TPITCH] = (float (*)[128][TPITCH])(smem_dyn + 2 * 128 * TPITCH);

    int tid = threadIdx.x;
    int bm = blockIdx.y * 128, bn = blockIdx.x * 128;
    int lane = tid & 31, warp = tid >> 5;
    int quad = lane >> 2, tq = lane & 3;
    int wm = (warp & 1) * 64, wn = (warp >> 1) * 32;
    int rr = tid >> 3, cc = tid & 7;

    float acc[4][4][4];
#pragma unroll
    for (int i = 0; i < 4; i++)
#pragma unroll
        for (int j = 0; j < 4; j++)
#pragma unroll
            for (int f = 0; f < 4; f++) acc[i][j][f] = 0.f;

#pragma unroll
    for (int i = 0; i < 4; i++) {
        int r = rr + i * 32;
        cp16(&Bs[0][r][cc * 4], B + (size_t)(bn + r) * K + cc * 4, bn + r < N);
        if (!CVTA)
            cp16(&As[0][r][cc * 4], A + (size_t)(bm + r) * K + cc * 4, true);
    }
    asm volatile("cp.async.commit_group;" ::: "memory");
    if (CVTA) {
#pragma unroll
        for (int i = 0; i < 4; i++) {
            float4 v = *(const float4*)(A + (size_t)(bm + rr + i * 32) * K + cc * 4);
            v.x = to_tf32(v.x); v.y = to_tf32(v.y);
            v.z = to_tf32(v.z); v.w = to_tf32(v.w);
            *(float4*)&As[0][rr + i * 32][cc * 4] = v;
        }
    }

    int nIter = K >> 5;
    for (int it = 0; it < nIter; it++) {
        int cur = it & 1, nb = cur ^ 1;
        bool more = (it + 1 < nIter);

        asm volatile("cp.async.wait_group 0;" ::: "memory");
        __syncthreads();

        if (more) {
            int k0 = (it + 1) << 5;
#pragma unroll
            for (int i = 0; i < 4; i++) {
                int r = rr + i * 32;
                cp16(&Bs[nb][r][cc * 4], B + (size_t)(bn + r) * K + k0 + cc * 4,
                     bn + r < N);
                if (!CVTA)
                    cp16(&As[nb][r][cc * 4], A + (size_t)(bm + r) * K + k0 + cc * 4,
                         true);
            }
            asm volatile("cp.async.commit_group;" ::: "memory");
        }

        __align__(16) unsigned bq[4][8];
#pragma unroll
        for (int j = 0; j < 4; j++) {
            const float* bp = &Bs[cur][wn + j * 8 + quad][tq * 8];
            *(float4*)&bq[j][0] = *(const float4*)bp;
            *(float4*)&bq[j][4] = *(const float4*)(bp + 4);
        }
#pragma unroll
        for (int i = 0; i < 4; i++) {
            __align__(16) unsigned alo[8], ahi[8];
            const float* ap0 = &As[cur][wm + i * 16 + quad][tq * 8];
            const float* ap1 = &As[cur][wm + i * 16 + 8 + quad][tq * 8];
            *(float4*)&alo[0] = *(const float4*)ap0;
            *(float4*)&alo[4] = *(const float4*)(ap0 + 4);
            *(float4*)&ahi[0] = *(const float4*)ap1;
            *(float4*)&ahi[4] = *(const float4*)(ap1 + 4);
#pragma unroll
            for (int j = 0; j < 4; j++)
#pragma unroll
                for (int s = 0; s < 4; s++)
                    mma8(acc[i][j], alo[2 * s], ahi[2 * s], alo[2 * s + 1],
                         ahi[2 * s + 1], bq[j][2 * s], bq[j][2 * s + 1]);
        }

        if (CVTA && more) {
            int k0 = (it + 1) << 5;
#pragma unroll
            for (int i = 0; i < 4; i++) {
                float4 v = *(const float4*)(A + (size_t)(bm + rr + i * 32) * K + k0 + cc * 4);
                v.x = to_tf32(v.x); v.y = to_tf32(v.y);
                v.z = to_tf32(v.z); v.w = to_tf32(v.w);
                *(float4*)&As[nb][rr + i * 32][cc * 4] = v;
            }
        }
    }

#pragma unroll
    for (int i = 0; i < 4; i++) {
        int row = bm + wm + i * 16 + quad;
#pragma unroll
        for (int j = 0; j < 4; j++) {
            int col = bn + wn + j * 8 + tq * 2;
            if (col < N) {
                float2 v0 = make_float2(acc[i][j][0], acc[i][j][1]);
                float2 v1 = make_float2(acc[i][j][2], acc[i][j][3]);
                *(float2*)(C + (size_t)row * N + col) = v0;
                *(float2*)(C + (size_t)(row + 8) * N + col) = v1;
            }
        }
    }
}

// ---------------- causal depthwise conv + silu (tanh-based, 1 MUFU) --------
__global__ __launch_bounds__(256) void k_conv(const float* __restrict__ cw,
                                              const float* __restrict__ cb) {
    int idx = blockIdx.x * 256 + threadIdx.x;
    int c = idx % CCH;
    int row = idx / CCH;
    int t = row & (LL - 1);
    const float* base = g_zx + (size_t)row * PRJ + DI + c;
    float acc = cb[c];
#pragma unroll
    for (int k = 0; k < DCV; k++) {
        int tt = t + k - (DCV - 1);
        if (tt >= 0) acc += base[(long)(k - (DCV - 1)) * PRJ] * cw[k * CCH + c];
    }
    g_xbc[(size_t)row * CCH + c] = silu_f(acc);
}

// ---------------- dt/dA: packed (dA, dt) float2 -----------------------------
__global__ __launch_bounds__(256) void k_dt(const float* __restrict__ dtb,
                                            const float* __restrict__ alog) {
    int idx = blockIdx.x * 256 + threadIdx.x;
    int row = idx >> 3, hh = idx & 7;
    float v = g_zx[(size_t)row * PRJ + DI + CCH + hh] + dtb[hh];
    float dt = (v > 20.f) ? v : log1pf(expf(v));
    float A = -expf(alog[hh]);
    g_sc[idx] = make_float2(expf(dt * A), dt);
}

// ---------------- sequential SSM scan (R9 structure, tanh silu) -------------
__global__ __launch_bounds__(256) void k_scan(const float* __restrict__ Dp) {
    int bh = blockIdx.x, b = bh >> 3, hh = bh & 7;
    int tid = threadIdx.x;
    int pg = tid >> 4, ng = tid & 15;
    int p0 = pg * 4, n0 = ng * 8;

    unsigned long long hs[4][4];
#pragma unroll
    for (int i = 0; i < 4; i++)
#pragma unroll
        for (int j = 0; j < 4; j++) hs[i][j] = 0ull;

    const float* xr = g_xbc + (size_t)b * LL * CCH;
    const int OB = DI + n0;
    const int OC = DI + DS + n0;
    const int OX = hh * HPP + p0;
    const float2* scp = g_sc + (size_t)b * LL * NHH + hh;
    const float* zp = g_zx + (size_t)b * LL * PRJ + hh * HPP + p0;
    float* yp = g_y + (size_t)b * LL * DI + hh * HPP + p0;
    float Dh = Dp[hh];
    bool ldz = (ng == 0);

    float4 pb0 = *(const float4*)(xr + OB);
    float4 pb1 = *(const float4*)(xr + OB + 4);
    float4 pc0 = *(const float4*)(xr + OC);
    float4 pc1 = *(const float4*)(xr + OC + 4);
    float4 px  = *(const float4*)(xr + OX);
    float2 psc = *scp;
    float4 pz = make_float4(0.f, 0.f, 0.f, 0.f);
    if (ldz) pz = *(const float4*)zp;

    for (int t = 0; t < LL; t++) {
        float4 vb0 = pb0, vb1 = pb1, vc0 = pc0, vc1 = pc1, vx = px, vz = pz;
        float2 vsc = psc;
        if (t + 1 < LL) {
            xr += CCH;
            scp += NHH;
            pb0 = *(const float4*)(xr + OB);
            pb1 = *(const float4*)(xr + OB + 4);
            pc0 = *(const float4*)(xr + OC);
            pc1 = *(const float4*)(xr + OC + 4);
            px  = *(const float4*)(xr + OX);
            psc = *scp;
            if (ldz) pz = *(const float4*)(zp + PRJ);
        }

        unsigned long long dA2 = pk2(vsc.x, vsc.x);
        float xa[4] = {vx.x, vx.y, vx.z, vx.w};
        unsigned long long bp[4], cp[4], dtx2[4], accp[4];
        bp[0] = pk2(vb0.x, vb0.y); bp[1] = pk2(vb0.z, vb0.w);
        bp[2] = pk2(vb1.x, vb1.y); bp[3] = pk2(vb1.z, vb1.w);
        cp[0] = pk2(vc0.x, vc0.y); cp[1] = pk2(vc0.z, vc0.w);
        cp[2] = pk2(vc1.x, vc1.y); cp[3] = pk2(vc1.z, vc1.w);
#pragma unroll
        for (int i = 0; i < 4; i++) {
            float d = vsc.y * xa[i];
            dtx2[i] = pk2(d, d);
            accp[i] = 0ull;
        }
#pragma unroll
        for (int i = 0; i < 4; i++)
#pragma unroll
            for (int j = 0; j < 4; j++) {
                hs[i][j] = fma2(dtx2[i], bp[j], mul2(hs[i][j], dA2));
                accp[i] = fma2(hs[i][j], cp[j], accp[i]);
            }
        float acc[4];
#pragma unroll
        for (int i = 0; i < 4; i++) {
            float lo, hi;
            upk2(lo, hi, accp[i]);
            acc[i] = lo + hi;
        }
#pragma unroll
        for (int o = 8; o > 0; o >>= 1)
#pragma unroll
            for (int i = 0; i < 4; i++)
                acc[i] += __shfl_down_sync(0xffffffffu, acc[i], o, 16);
        if (ldz) {
            float za[4] = {vz.x, vz.y, vz.z, vz.w};
            float4 yo;
            float* yv = &yo.x;
#pragma unroll
            for (int i = 0; i < 4; i++)
                yv[i] = (acc[i] + Dh * xa[i]) * silu_f(za[i]);
            *(float4*)yp = yo;
            zp += PRJ;
            yp += DI;
        }
    }
}

// ---------------- RMS norm over 512 (in place; writes permuted + tf32) -----
__global__ __launch_bounds__(256) void k_rms(const float* __restrict__ nw) {
    int row = blockIdx.x, j = threadIdx.x;
    float a0 = g_y[(size_t)row * DI + j];
    float a1 = g_y[(size_t)row * DI + 256 + j];
    float v = a0 * a0 + a1 * a1;
    __shared__ float s1[8];
    int lane = j & 31, w = j >> 5;
#pragma unroll
    for (int o = 16; o > 0; o >>= 1) v += __shfl_down_sync(0xffffffffu, v, o);
    if (lane == 0) s1[w] = v;
    __syncthreads();
    if (j == 0) {
        float a = 0.f;
#pragma unroll
        for (int i = 0; i < 8; i++) a += s1[i];
        s1[0] = a * (1.f / DI);
    }
    __syncthreads();
    float sc = rsqrtf(s1[0] + EPSF);
    int pj = permc(j);
    g_y[(size_t)row * DI + pj]       = to_tf32(a0 * sc * nw[j]);
    g_y[(size_t)row * DI + 256 + pj] = to_tf32(a1 * sc * nw[j + 256]);
}

// ---------------- residual add + layernorm (g_h permuted in/out) ------------
__global__ __launch_bounds__(256) void k_addln(const float* __restrict__ lw,
                                               const float* __restrict__ lb) {
    int row = blockIdx.x, j = threadIdx.x;
    float acc = g_m[(size_t)row * DM + j] + g_h[(size_t)row * DM + permc(j)];
    ln_write256(acc, g_h + (size_t)row * DM, lw, lb, j);
}

// ---------------- masked mean pool (permuted cols, 8 t-slices) --------------
__global__ __launch_bounds__(256) void k_pool(const int* __restrict__ lengths) {
    int b = blockIdx.x, s = blockIdx.y, d = threadIdx.x;
    int len = lengths[b];
    int t0 = s * 128;
    int t1 = min(t0 + 128, len);
    float acc = 0.f;
    const float* base = g_h + ((size_t)b * LL + t0) * DM + d;
#pragma unroll 4
    for (int t = t0; t < t1; t++, base += DM) acc += *base;
    g_poolp[s][b * DM + d] = acc;
}

// ---------------- classification head ---------------------------------------
__global__ __launch_bounds__(NCLS*32) void k_head(const float* __restrict__ hw,
                                                  const float* __restrict__ hb,
                                                  const int* __restrict__ lengths,
                                                  float* __restrict__ out) {
    int b = blockIdx.x;
    int tid = threadIdx.x, c = tid >> 5, lane = tid & 31;
    __shared__ float sp[DM];
    if (tid < DM) {
        float a = 0.f;
#pragma unroll
        for (int s = 0; s < 8; s++) a += g_poolp[s][b * DM + tid];
        sp[permcinv(tid)] = a / (float)lengths[b];
    }
    __syncthreads();
    float acc = 0.f;
    for (int k = lane; k < DM; k += 32) acc += sp[k] * hw[c * DM + k];
#pragma unroll
    for (int o = 16; o > 0; o >>= 1) acc += __shfl_down_sync(0xffffffffu, acc, o);
    if (lane == 0) out[b * NCLS + c] = acc + hb[c];
}

// ---------------- launcher ---------------------------------------------------
extern "C" void kernel_launch(void* const* d_in, const int* in_sizes, int n_in,
                              void* d_out, int out_size) {
    (void)in_sizes; (void)n_in; (void)out_size;
    const float* x        = (const float*)d_in[0];
    const float* in_w     = (const float*)d_in[1];
    const float* in_b     = (const float*)d_in[2];
    const float* lnin_w   = (const float*)d_in[3];
    const float* lnin_b   = (const float*)d_in[4];
    const float* inproj_w = (const float*)d_in[5];
    const float* conv_w   = (const float*)d_in[6];
    const float* conv_b   = (const float*)d_in[7];
    const float* dt_bias  = (const float*)d_in[8];
    const float* A_log    = (const float*)d_in[9];
    const float* Dp       = (const float*)d_in[10];
    const float* norm_w   = (const float*)d_in[11];
    const float* outp_w   = (const float*)d_in[12];
    const float* ln_w     = (const float*)d_in[13];
    const float* ln_b     = (const float*)d_in[14];
    const float* head_w   = (const float*)d_in[15];
    const float* head_b   = (const float*)d_in[16];
    const int*   lengths  = (const int*)d_in[17];
    float* out = (float*)d_out;

    float *ph, *pzx, *py, *pm, *pwin, *pwout;
    cudaGetSymbolAddress((void**)&ph,    g_h);
    cudaGetSymbolAddress((void**)&pzx,   g_zx);
    cudaGetSymbolAddress((void**)&py,    g_y);
    cudaGetSymbolAddress((void**)&pm,    g_m);
    cudaGetSymbolAddress((void**)&pwin,  g_win);
    cudaGetSymbolAddress((void**)&pwout, g_wout);

    cudaFuncSetAttribute(gemm_tf32<true>,  cudaFuncAttributeMaxDynamicSharedMemorySize,
                         GEMM_SMEM);
    cudaFuncSetAttribute(gemm_tf32<false>, cudaFuncAttributeMaxDynamicSharedMemorySize,
                         GEMM_SMEM);

    int totIn  = NLAYER * PRJ * DM;
    int totOut = NLAYER * DM * DI;
    k_permw<<<(totIn  + 255) / 256, 256>>>(inproj_w, pwin,  totIn,  DM - 1);
    k_permw<<<(totOut + 255) / 256, 256>>>(outp_w,   pwout, totOut, DI - 1);

    k_in_ln<<<BLT, 256>>>(x, in_w, in_b, lnin_w, lnin_b);
    for (int i = 0; i < NLAYER; i++) {
        gemm_tf32<true><<<dim3((PRJ + 127) / 128, BLT / 128), 256, GEMM_SMEM>>>(
            ph, pwin + (size_t)i * PRJ * DM, pzx, BLT, PRJ, DM);
        k_conv<<<(BLT * CCH) / 256, 256>>>(conv_w + i * DCV * CCH, conv_b + i * CCH);
        k_dt<<<(BLT * NHH) / 256, 256>>>(dt_bias + i * NHH, A_log + i * NHH);
        k_scan<<<BB * NHH, 256>>>(Dp + i * NHH);
        k_rms<<<BLT, 256>>>(norm_w + i * DI);
        gemm_tf32<false><<<dim3(DM / 128, BLT / 128), 256, GEMM_SMEM>>>(
            py, pwout + (size_t)i * DM * DI, pm, BLT, DM, DI);
        k_addln<<<BLT, 256>>>(ln_w + i * DM, ln_b + i * DM);
    }
    k_pool<<<dim3(BB, 8), 256>>>(lengths);
    k_head<<<BB, NCLS * 32>>>(head_w, head_b, lengths, out);
}